// round 2
// baseline (speedup 1.0000x reference)
#include <cuda_runtime.h>
#include <math.h>

#define TT 64
#define BB 32
#define SS 64
#define HH 1024
#define EE 1024

// ---------------- scratch (static device globals; no allocations) ----------------
__device__ float g_emb[TT * BB * EE];      // gathered embeddings [T,B,E]
__device__ float g_h0[BB * HH];
__device__ float g_h1[BB * HH];
__device__ float g_c0[BB * HH];
__device__ float g_c1[BB * HH];
__device__ float g_feed[BB * HH];
__device__ float g_g0p[3 * BB * 4 * HH];   // layer0 gate partials (3 pieces)
__device__ float g_g1p[2 * BB * 4 * HH];   // layer1 gate partials (2 pieces)
__device__ float g_qp[4 * BB * HH];        // q partials (K split 4)
__device__ float g_pop[4 * BB * HH];       // pre-output partials (2 pieces x K split 2)
__device__ float g_cvec[BB * HH];

struct Piece { const float* W; const float* X; int ldw; int col; };

// ---------------- embedding gather ----------------
__global__ void embed_kernel(const int* __restrict__ ids, const float* __restrict__ emb) {
    int tb = blockIdx.x;                     // 0 .. T*B-1
    int id = ids[tb];
    const float4* src = (const float4*)(emb + (size_t)id * EE);
    float4* dst = (float4*)(g_emb + (size_t)tb * EE);
    dst[threadIdx.x] = src[threadIdx.x];     // 256 threads * float4 = 1024 floats
}

__global__ void init_kernel(const float* __restrict__ h0in, const float* __restrict__ c0in) {
    int i = blockIdx.x * 256 + threadIdx.x;
    if (i < BB * HH) {
        g_h0[i] = h0in[i];
        g_h1[i] = h0in[BB * HH + i];
        g_c0[i] = c0in[i];
        g_c1[i] = c0in[BB * HH + i];
        g_feed[i] = 0.f;
    }
}

// ---------------- fp32 GEMM over one K=1024 "piece" ----------------
// out[pidx][b][row] = sum_k W[row][col+k] * X[b][k]   (partials, reduced later)
// grid: (M/32, nPieces, kSplit). 256 threads: thread = (row r=tid>>3, batch-quad bq=tid&7)
__global__ void gemm_kernel(Piece p0, Piece p1, Piece p2, float* __restrict__ out, int M) {
    Piece p = p0;
    if (blockIdx.y == 1) p = p1;
    else if (blockIdx.y == 2) p = p2;
    const int kChunk = 1024 / gridDim.z;
    const int kbase  = blockIdx.z * kChunk;
    const int pidx   = blockIdx.y * gridDim.z + blockIdx.z;

    __shared__ float xs[128][33];            // [k][b], pad 33 -> conflict free
    int tid = threadIdx.x;
    int r   = tid >> 3;                      // 0..31
    int bq  = (tid & 7) << 2;                // batch base 0,4,...,28
    int row = blockIdx.x * 32 + r;

    const float* Wp = p.W + (size_t)row * p.ldw + p.col + kbase;
    const float* X  = p.X + kbase;           // row stride stays 1024

    float a0 = 0.f, a1 = 0.f, a2 = 0.f, a3 = 0.f;
    for (int kt = 0; kt < kChunk; kt += 128) {
        #pragma unroll
        for (int i = 0; i < 16; i++) {       // 4096 floats / 256 threads
            int f = tid + i * 256;
            xs[f & 127][f >> 7] = X[(f >> 7) * 1024 + kt + (f & 127)];
        }
        __syncthreads();
        #pragma unroll 8
        for (int k = 0; k < 128; k++) {
            float w = __ldg(Wp + kt + k);
            a0 = fmaf(w, xs[k][bq + 0], a0);
            a1 = fmaf(w, xs[k][bq + 1], a1);
            a2 = fmaf(w, xs[k][bq + 2], a2);
            a3 = fmaf(w, xs[k][bq + 3], a3);
        }
        __syncthreads();
    }
    float* o = out + (size_t)pidx * BB * M;
    o[(bq + 0) * M + row] = a0;
    o[(bq + 1) * M + row] = a1;
    o[(bq + 2) * M + row] = a2;
    o[(bq + 3) * M + row] = a3;
}

__device__ __forceinline__ float sigm(float x) { return 1.f / (1.f + expf(-x)); }

// ---------------- LSTM cell pointwise (reduces gate partials + bias) ----------------
__global__ void cell_kernel(const float* __restrict__ gp, int np,
                            const float* __restrict__ b_ih, const float* __restrict__ b_hh,
                            float* __restrict__ h, float* __restrict__ c) {
    int idx = blockIdx.x * 256 + threadIdx.x;
    if (idx >= BB * HH) return;
    int b = idx >> 10, hh = idx & 1023;
    float gi = 0.f, gf = 0.f, gg = 0.f, go = 0.f;
    for (int p = 0; p < np; p++) {
        const float* g = gp + (size_t)p * BB * 4 * HH + (size_t)b * 4 * HH;
        gi += g[hh];
        gf += g[HH + hh];
        gg += g[2 * HH + hh];
        go += g[3 * HH + hh];
    }
    gi += b_ih[hh]          + b_hh[hh];
    gf += b_ih[HH + hh]     + b_hh[HH + hh];
    gg += b_ih[2 * HH + hh] + b_hh[2 * HH + hh];
    go += b_ih[3 * HH + hh] + b_hh[3 * HH + hh];
    float cn = sigm(gf) * c[idx] + sigm(gi) * tanhf(gg);
    c[idx] = cn;
    h[idx] = sigm(go) * tanhf(cn);
}

// ---------------- attention: scores + masked softmax + context vector ----------------
__global__ void attn_kernel(const float* __restrict__ ctx, const int* __restrict__ lens,
                            float* __restrict__ attn_out, int t) {
    int b = blockIdx.x;
    int tid = threadIdx.x;
    __shared__ float qs[HH];
    __shared__ float sc[SS];

    for (int i = tid; i < HH; i += 256)
        qs[i] = g_qp[0 * BB * HH + b * HH + i] + g_qp[1 * BB * HH + b * HH + i]
              + g_qp[2 * BB * HH + b * HH + i] + g_qp[3 * BB * HH + b * HH + i];
    __syncthreads();

    int w = tid >> 5, lane = tid & 31;       // 8 warps, each handles 8 s-values
    #pragma unroll
    for (int si = 0; si < 8; si++) {
        int s = si * 8 + w;
        const float* cr = ctx + ((size_t)s * BB + b) * HH;   // context[s,b,:]
        float sum = 0.f;
        for (int i = lane; i < HH; i += 32) sum = fmaf(qs[i], cr[i], sum);
        #pragma unroll
        for (int o = 16; o > 0; o >>= 1) sum += __shfl_xor_sync(0xffffffffu, sum, o);
        if (lane == 0) sc[s] = sum;
    }
    __syncthreads();

    if (tid == 0) {
        int len = lens[b];
        len = len < 1 ? 1 : (len > SS ? SS : len);
        float m = sc[0];
        for (int s = 1; s < len; s++) m = fmaxf(m, sc[s]);
        float sum = 0.f;
        for (int s = 0; s < len; s++) { float e = expf(sc[s] - m); sc[s] = e; sum += e; }
        float inv = 1.f / sum;
        for (int s = 0; s < len; s++) sc[s] *= inv;
        for (int s = len; s < SS; s++) sc[s] = 0.f;   // masked positions underflow to 0 in ref
    }
    __syncthreads();

    if (tid < SS) attn_out[((size_t)t * BB + b) * SS + tid] = sc[tid];

    float a0 = 0.f, a1 = 0.f, a2 = 0.f, a3 = 0.f;
    for (int s = 0; s < SS; s++) {
        float a = sc[s];
        const float* cr = ctx + ((size_t)s * BB + b) * HH;
        a0 = fmaf(a, cr[tid      ], a0);
        a1 = fmaf(a, cr[tid + 256], a1);
        a2 = fmaf(a, cr[tid + 512], a2);
        a3 = fmaf(a, cr[tid + 768], a3);
    }
    g_cvec[b * HH + tid      ] = a0;
    g_cvec[b * HH + tid + 256] = a1;
    g_cvec[b * HH + tid + 512] = a2;
    g_cvec[b * HH + tid + 768] = a3;
}

// ---------------- output epilogue: tanh, write outputs[t], update input feed ----------------
__global__ void outepi_kernel(float* __restrict__ outv, int t) {
    int idx = blockIdx.x * 256 + threadIdx.x;
    if (idx >= BB * HH) return;
    float v = g_pop[idx] + g_pop[BB * HH + idx] + g_pop[2 * BB * HH + idx] + g_pop[3 * BB * HH + idx];
    v = tanhf(v);
    outv[(size_t)t * BB * HH + idx] = v;
    g_feed[idx] = v;
}

// ---------------- launcher (graph-capturable: kernel launches only) ----------------
extern "C" void kernel_launch(void* const* d_in, const int* in_sizes, int n_in,
                              void* d_out, int out_size) {
    const int*   ids   = (const int*)  d_in[0];
    const float* ctx   = (const float*)d_in[1];
    const int*   lens  = (const int*)  d_in[2];
    const float* h0    = (const float*)d_in[3];
    const float* c0    = (const float*)d_in[4];
    const float* emb   = (const float*)d_in[5];
    const float* W_ih0 = (const float*)d_in[6];
    const float* W_hh0 = (const float*)d_in[7];
    const float* b_ih0 = (const float*)d_in[8];
    const float* b_hh0 = (const float*)d_in[9];
    const float* W_ih1 = (const float*)d_in[10];
    const float* W_hh1 = (const float*)d_in[11];
    const float* b_ih1 = (const float*)d_in[12];
    const float* b_hh1 = (const float*)d_in[13];
    const float* W_in  = (const float*)d_in[14];
    const float* W_out = (const float*)d_in[15];

    float* outv = (float*)d_out;                       // outputs [T,B,H]
    float* attn = outv + (size_t)TT * BB * HH;         // attns   [T,B,S]

    float *p_emb, *p_h0, *p_h1, *p_c0, *p_c1, *p_feed, *p_cvec, *p_g0, *p_g1, *p_q, *p_po;
    cudaGetSymbolAddress((void**)&p_emb,  g_emb);
    cudaGetSymbolAddress((void**)&p_h0,   g_h0);
    cudaGetSymbolAddress((void**)&p_h1,   g_h1);
    cudaGetSymbolAddress((void**)&p_c0,   g_c0);
    cudaGetSymbolAddress((void**)&p_c1,   g_c1);
    cudaGetSymbolAddress((void**)&p_feed, g_feed);
    cudaGetSymbolAddress((void**)&p_cvec, g_cvec);
    cudaGetSymbolAddress((void**)&p_g0,   g_g0p);
    cudaGetSymbolAddress((void**)&p_g1,   g_g1p);
    cudaGetSymbolAddress((void**)&p_q,    g_qp);
    cudaGetSymbolAddress((void**)&p_po,   g_pop);

    embed_kernel<<<TT * BB, 256>>>(ids, emb);
    init_kernel<<<(BB * HH + 255) / 256, 256>>>(h0, c0);

    for (int t = 0; t < TT; t++) {
        // layer 0 gates: W_ih0[:, :E] @ emb_t  +  W_ih0[:, E:] @ feed  +  W_hh0 @ h0
        Piece q0{W_ih0, p_emb + (size_t)t * BB * EE, 2 * HH, 0};
        Piece q1{W_ih0, p_feed, 2 * HH, HH};
        Piece q2{W_hh0, p_h0, HH, 0};
        gemm_kernel<<<dim3(4 * HH / 32, 3, 1), 256>>>(q0, q1, q2, p_g0, 4 * HH);
        cell_kernel<<<(BB * HH + 255) / 256, 256>>>(p_g0, 3, b_ih0, b_hh0, p_h0, p_c0);

        // layer 1 gates: W_ih1 @ h0_new + W_hh1 @ h1_prev
        Piece r0{W_ih1, p_h0, HH, 0};
        Piece r1{W_hh1, p_h1, HH, 0};
        gemm_kernel<<<dim3(4 * HH / 32, 2, 1), 256>>>(r0, r1, r1, p_g1, 4 * HH);
        cell_kernel<<<(BB * HH + 255) / 256, 256>>>(p_g1, 2, b_ih1, b_hh1, p_h1, p_c1);

        // q = W_in @ h1   (K split 4 for occupancy)
        Piece s0{W_in, p_h1, HH, 0};
        gemm_kernel<<<dim3(HH / 32, 1, 4), 256>>>(s0, s0, s0, p_q, HH);

        attn_kernel<<<BB, 256>>>(ctx, lens, attn, t);

        // pre-output = W_out[:, :H] @ c_vec + W_out[:, H:] @ h1  (2 pieces x K split 2)
        Piece u0{W_out, p_cvec, 2 * HH, 0};
        Piece u1{W_out, p_h1, 2 * HH, HH};
        gemm_kernel<<<dim3(HH / 32, 2, 2), 256>>>(u0, u1, u1, p_po, HH);

        outepi_kernel<<<(BB * HH + 255) / 256, 256>>>(outv, t);
    }
}

// round 3
// speedup vs baseline: 2.3983x; 2.3983x over previous
#include <cuda_runtime.h>
#include <math.h>

#define TT 64
#define BB 32
#define SS 64
#define HH 1024
#define EE 1024

// ---------------- scratch (static device globals; no allocations) ----------------
// All activations stored TRANSPOSED: xT[k][b] (b fastest, 32-wide) for coalesced GEMM loads.
__device__ float g_embT[TT * EE * BB];     // [t][e][b]
__device__ float g_h0T[HH * BB];
__device__ float g_h1T[HH * BB];
__device__ float g_c0T[HH * BB];
__device__ float g_c1T[HH * BB];
__device__ float g_feedT[HH * BB];
__device__ float g_cvecT[HH * BB];
__device__ float g_g0p[6 * 4 * HH * BB];   // layer0 gate partials: 3 pieces x ksplit2, [p][row][b]
__device__ float g_g1p[4 * 4 * HH * BB];   // layer1: 2 pieces x ksplit2
__device__ float g_qp[8 * HH * BB];        // q: 1 piece x ksplit8
__device__ float g_pop[8 * HH * BB];       // pre-output: 2 pieces x ksplit4

struct Piece { const float* W; const float* X; int ldw; int col; };

// ---------------- embedding gather + transpose ----------------
// grid: T * (E/32) blocks; block handles one t and a 32-wide e-tile for all 32 b.
__global__ void embed_kernel(const int* __restrict__ ids, const float* __restrict__ emb) {
    __shared__ float sh[32][33];
    int t = blockIdx.x >> 5;
    int etile = (blockIdx.x & 31) * 32;
    int w = threadIdx.x >> 5, lane = threadIdx.x & 31;
    #pragma unroll
    for (int i = 0; i < 4; i++) {
        int b = w + i * 8;
        int id = ids[t * BB + b];
        sh[b][lane] = emb[(size_t)id * EE + etile + lane];   // coalesced read
    }
    __syncthreads();
    #pragma unroll
    for (int i = 0; i < 4; i++) {
        int e = w + i * 8;
        g_embT[((size_t)t * EE + etile + e) * BB + lane] = sh[lane][e];  // coalesced write
    }
}

__global__ void init_kernel(const float* __restrict__ h0in, const float* __restrict__ c0in) {
    int idx = blockIdx.x * 256 + threadIdx.x;
    if (idx < BB * HH) {
        int b = idx >> 10, hh = idx & 1023;
        int tr = hh * BB + b;
        g_h0T[tr] = h0in[idx];
        g_h1T[tr] = h0in[BB * HH + idx];
        g_c0T[tr] = c0in[idx];
        g_c1T[tr] = c0in[BB * HH + idx];
        g_feedT[tr] = 0.f;
    }
}

// ---------------- fp32 register-tiled GEMM ----------------
// out[pidx][row][b] = sum_k W[row][col+k] * X[k][b]   (partials, reduced later)
// grid: (M/64, nPieces, kSplit), 128 threads. Thread: 4 rows x 4 batches.
__global__ void __launch_bounds__(128, 4)
gemm2_kernel(Piece p0, Piece p1, Piece p2, float* __restrict__ out, int M) {
    Piece p = p0;
    if (blockIdx.y == 1) p = p1;
    else if (blockIdx.y == 2) p = p2;
    const int kChunk = 1024 / gridDim.z;
    const int kbase  = blockIdx.z * kChunk;
    const int pidx   = blockIdx.y * gridDim.z + blockIdx.z;

    __shared__ float Ws[64][132];   // [row][k], pad for bank spread, float4-aligned
    __shared__ float xs[128][36];   // [k][b],  pad 36 (float4-aligned)

    int tid = threadIdx.x;
    int rt = tid >> 3;              // 0..15 -> 4 rows each
    int bt = tid & 7;               // 0..7  -> 4 batches each
    int rowBase = blockIdx.x * 64;

    const float* Wbase = p.W + (size_t)rowBase * p.ldw + p.col + kbase;
    const float* X     = p.X + (size_t)kbase * BB;

    float acc[4][4];
    #pragma unroll
    for (int i = 0; i < 4; i++)
        #pragma unroll
        for (int j = 0; j < 4; j++) acc[i][j] = 0.f;

    for (int kt = 0; kt < kChunk; kt += 128) {
        // load W chunk: 64 rows x 128 k (coalesced float4 per row)
        #pragma unroll
        for (int i = 0; i < 16; i++) {
            int f4 = tid + i * 128;
            int row = f4 >> 5, kq = f4 & 31;
            float4 w = __ldg((const float4*)(Wbase + (size_t)row * p.ldw + kt + kq * 4));
            *(float4*)&Ws[row][kq * 4] = w;
        }
        // load x chunk: 128 k x 32 b (fully coalesced float4)
        #pragma unroll
        for (int i = 0; i < 8; i++) {
            int f4 = tid + i * 128;
            int k = f4 >> 3, bq = f4 & 7;
            float4 v = __ldg((const float4*)(X + (size_t)(kt + k) * BB + bq * 4));
            *(float4*)&xs[k][bq * 4] = v;
        }
        __syncthreads();

        #pragma unroll 4
        for (int kq = 0; kq < 32; kq++) {
            float4 xv0 = *(const float4*)&xs[kq * 4 + 0][bt * 4];
            float4 xv1 = *(const float4*)&xs[kq * 4 + 1][bt * 4];
            float4 xv2 = *(const float4*)&xs[kq * 4 + 2][bt * 4];
            float4 xv3 = *(const float4*)&xs[kq * 4 + 3][bt * 4];
            #pragma unroll
            for (int i = 0; i < 4; i++) {
                float4 w = *(const float4*)&Ws[rt * 4 + i][kq * 4];
                acc[i][0] = fmaf(w.x, xv0.x, acc[i][0]);
                acc[i][0] = fmaf(w.y, xv1.x, acc[i][0]);
                acc[i][0] = fmaf(w.z, xv2.x, acc[i][0]);
                acc[i][0] = fmaf(w.w, xv3.x, acc[i][0]);
                acc[i][1] = fmaf(w.x, xv0.y, acc[i][1]);
                acc[i][1] = fmaf(w.y, xv1.y, acc[i][1]);
                acc[i][1] = fmaf(w.z, xv2.y, acc[i][1]);
                acc[i][1] = fmaf(w.w, xv3.y, acc[i][1]);
                acc[i][2] = fmaf(w.x, xv0.z, acc[i][2]);
                acc[i][2] = fmaf(w.y, xv1.z, acc[i][2]);
                acc[i][2] = fmaf(w.z, xv2.z, acc[i][2]);
                acc[i][2] = fmaf(w.w, xv3.z, acc[i][2]);
                acc[i][3] = fmaf(w.x, xv0.w, acc[i][3]);
                acc[i][3] = fmaf(w.y, xv1.w, acc[i][3]);
                acc[i][3] = fmaf(w.z, xv2.w, acc[i][3]);
                acc[i][3] = fmaf(w.w, xv3.w, acc[i][3]);
            }
        }
        __syncthreads();
    }

    float* o = out + (size_t)pidx * M * BB;
    #pragma unroll
    for (int i = 0; i < 4; i++) {
        int row = rowBase + rt * 4 + i;
        *(float4*)&o[(size_t)row * BB + bt * 4] =
            make_float4(acc[i][0], acc[i][1], acc[i][2], acc[i][3]);
    }
}

__device__ __forceinline__ float sigm(float x) { return 1.f / (1.f + expf(-x)); }

// ---------------- LSTM cell pointwise; partials layout [p][row][b] ----------------
__global__ void cell_kernel(const float* __restrict__ gp, int np,
                            const float* __restrict__ b_ih, const float* __restrict__ b_hh,
                            float* __restrict__ hT, float* __restrict__ cT) {
    int idx = blockIdx.x * 256 + threadIdx.x;
    if (idx >= BB * HH) return;
    int hh = idx >> 5, b = idx & 31;
    float gi = 0.f, gf = 0.f, gg = 0.f, go = 0.f;
    for (int p = 0; p < np; p++) {
        const float* g = gp + (size_t)p * 4 * HH * BB;
        gi += g[(size_t)hh * BB + b];
        gf += g[(size_t)(HH + hh) * BB + b];
        gg += g[(size_t)(2 * HH + hh) * BB + b];
        go += g[(size_t)(3 * HH + hh) * BB + b];
    }
    gi += b_ih[hh]          + b_hh[hh];
    gf += b_ih[HH + hh]     + b_hh[HH + hh];
    gg += b_ih[2 * HH + hh] + b_hh[2 * HH + hh];
    go += b_ih[3 * HH + hh] + b_hh[3 * HH + hh];
    float cn = sigm(gf) * cT[idx] + sigm(gi) * tanhf(gg);
    cT[idx] = cn;
    hT[idx] = sigm(go) * tanhf(cn);
}

// ---------------- attention: scores + masked softmax + context vector ----------------
__global__ void attn_kernel(const float* __restrict__ ctx, const int* __restrict__ lens,
                            float* __restrict__ attn_out, int t) {
    int b = blockIdx.x;
    int tid = threadIdx.x;
    __shared__ float qs[HH];
    __shared__ float sc[SS];

    for (int i = tid; i < HH; i += 256) {
        float s = 0.f;
        #pragma unroll
        for (int p = 0; p < 8; p++)
            s += g_qp[((size_t)p * HH + i) * BB + b];
        qs[i] = s;
    }
    __syncthreads();

    int w = tid >> 5, lane = tid & 31;       // 8 warps, each handles 8 s-values
    #pragma unroll
    for (int si = 0; si < 8; si++) {
        int s = si * 8 + w;
        const float* cr = ctx + ((size_t)s * BB + b) * HH;   // context[s,b,:]
        float sum = 0.f;
        for (int i = lane; i < HH; i += 32) sum = fmaf(qs[i], cr[i], sum);
        #pragma unroll
        for (int o = 16; o > 0; o >>= 1) sum += __shfl_xor_sync(0xffffffffu, sum, o);
        if (lane == 0) sc[s] = sum;
    }
    __syncthreads();

    if (tid == 0) {
        int len = lens[b];
        len = len < 1 ? 1 : (len > SS ? SS : len);
        float m = sc[0];
        for (int s = 1; s < len; s++) m = fmaxf(m, sc[s]);
        float sum = 0.f;
        for (int s = 0; s < len; s++) { float e = expf(sc[s] - m); sc[s] = e; sum += e; }
        float inv = 1.f / sum;
        for (int s = 0; s < len; s++) sc[s] *= inv;
        for (int s = len; s < SS; s++) sc[s] = 0.f;
    }
    __syncthreads();

    if (tid < SS) attn_out[((size_t)t * BB + b) * SS + tid] = sc[tid];

    float a0 = 0.f, a1 = 0.f, a2 = 0.f, a3 = 0.f;
    for (int s = 0; s < SS; s++) {
        float a = sc[s];
        const float* cr = ctx + ((size_t)s * BB + b) * HH;
        a0 = fmaf(a, cr[tid      ], a0);
        a1 = fmaf(a, cr[tid + 256], a1);
        a2 = fmaf(a, cr[tid + 512], a2);
        a3 = fmaf(a, cr[tid + 768], a3);
    }
    g_cvecT[(size_t)(tid      ) * BB + b] = a0;
    g_cvecT[(size_t)(tid + 256) * BB + b] = a1;
    g_cvecT[(size_t)(tid + 512) * BB + b] = a2;
    g_cvecT[(size_t)(tid + 768) * BB + b] = a3;
}

// ---------------- output epilogue: reduce 8 partials, tanh, write output + feed ----------------
__global__ void outepi_kernel(float* __restrict__ outv, int t) {
    int idx = blockIdx.x * 256 + threadIdx.x;
    if (idx >= BB * HH) return;
    int hh = idx >> 5, b = idx & 31;
    float v = 0.f;
    #pragma unroll
    for (int p = 0; p < 8; p++)
        v += g_pop[(size_t)p * HH * BB + idx];
    v = tanhf(v);
    outv[((size_t)t * BB + b) * HH + hh] = v;
    g_feedT[idx] = v;
}

// ---------------- launcher (graph-capturable: kernel launches only) ----------------
extern "C" void kernel_launch(void* const* d_in, const int* in_sizes, int n_in,
                              void* d_out, int out_size) {
    const int*   ids   = (const int*)  d_in[0];
    const float* ctx   = (const float*)d_in[1];
    const int*   lens  = (const int*)  d_in[2];
    const float* h0    = (const float*)d_in[3];
    const float* c0    = (const float*)d_in[4];
    const float* emb   = (const float*)d_in[5];
    const float* W_ih0 = (const float*)d_in[6];
    const float* W_hh0 = (const float*)d_in[7];
    const float* b_ih0 = (const float*)d_in[8];
    const float* b_hh0 = (const float*)d_in[9];
    const float* W_ih1 = (const float*)d_in[10];
    const float* W_hh1 = (const float*)d_in[11];
    const float* b_ih1 = (const float*)d_in[12];
    const float* b_hh1 = (const float*)d_in[13];
    const float* W_in  = (const float*)d_in[14];
    const float* W_out = (const float*)d_in[15];

    float* outv = (float*)d_out;                       // outputs [T,B,H]
    float* attn = outv + (size_t)TT * BB * HH;         // attns   [T,B,S]

    float *p_embT, *p_h0T, *p_h1T, *p_feedT, *p_cvecT, *p_g0, *p_g1, *p_q, *p_po, *p_c0T, *p_c1T;
    cudaGetSymbolAddress((void**)&p_embT,  g_embT);
    cudaGetSymbolAddress((void**)&p_h0T,   g_h0T);
    cudaGetSymbolAddress((void**)&p_h1T,   g_h1T);
    cudaGetSymbolAddress((void**)&p_c0T,   g_c0T);
    cudaGetSymbolAddress((void**)&p_c1T,   g_c1T);
    cudaGetSymbolAddress((void**)&p_feedT, g_feedT);
    cudaGetSymbolAddress((void**)&p_cvecT, g_cvecT);
    cudaGetSymbolAddress((void**)&p_g0,    g_g0p);
    cudaGetSymbolAddress((void**)&p_g1,    g_g1p);
    cudaGetSymbolAddress((void**)&p_q,     g_qp);
    cudaGetSymbolAddress((void**)&p_po,    g_pop);

    embed_kernel<<<TT * (EE / 32), 256>>>(ids, emb);
    init_kernel<<<(BB * HH + 255) / 256, 256>>>(h0, c0);

    for (int t = 0; t < TT; t++) {
        // layer 0 gates: W_ih0[:, :E] @ emb_t + W_ih0[:, E:] @ feed + W_hh0 @ h0
        Piece q0{W_ih0, p_embT + (size_t)t * EE * BB, 2 * HH, 0};
        Piece q1{W_ih0, p_feedT, 2 * HH, HH};
        Piece q2{W_hh0, p_h0T, HH, 0};
        gemm2_kernel<<<dim3(4 * HH / 64, 3, 2), 128>>>(q0, q1, q2, p_g0, 4 * HH);
        cell_kernel<<<(BB * HH + 255) / 256, 256>>>(p_g0, 6, b_ih0, b_hh0, p_h0T, p_c0T);

        // layer 1 gates: W_ih1 @ h0_new + W_hh1 @ h1_prev
        Piece r0{W_ih1, p_h0T, HH, 0};
        Piece r1{W_hh1, p_h1T, HH, 0};
        gemm2_kernel<<<dim3(4 * HH / 64, 2, 2), 128>>>(r0, r1, r1, p_g1, 4 * HH);
        cell_kernel<<<(BB * HH + 255) / 256, 256>>>(p_g1, 4, b_ih1, b_hh1, p_h1T, p_c1T);

        // q = W_in @ h1   (K split 8 for occupancy: 128 blocks)
        Piece s0{W_in, p_h1T, HH, 0};
        gemm2_kernel<<<dim3(HH / 64, 1, 8), 128>>>(s0, s0, s0, p_q, HH);

        attn_kernel<<<BB, 256>>>(ctx, lens, attn, t);

        // pre-output = W_out[:, :H] @ c_vec + W_out[:, H:] @ h1  (2 pieces x K split 4)
        Piece u0{W_out, p_cvecT, 2 * HH, 0};
        Piece u1{W_out, p_h1T, 2 * HH, HH};
        gemm2_kernel<<<dim3(HH / 64, 2, 4), 128>>>(u0, u1, u1, p_po, HH);

        outepi_kernel<<<(BB * HH + 255) / 256, 256>>>(outv, t);
    }
}

// round 5
// speedup vs baseline: 2.4269x; 1.0119x over previous
#include <cuda_runtime.h>
#include <math.h>

#define TT 64
#define BB 32
#define SS 64
#define HH 1024
#define EE 1024

// ---------------- scratch (static device globals; no allocations) ----------------
// All activations stored TRANSPOSED: xT[k][b] (b fastest, 32-wide) for coalesced GEMM loads.
__device__ float g_embT[TT * EE * BB];     // [t][e][b]
__device__ float g_h0T[HH * BB];
__device__ float g_h1T[HH * BB];
__device__ float g_c0T[HH * BB];
__device__ float g_c1T[HH * BB];
__device__ float g_feedT[HH * BB];
__device__ float g_cvecT[HH * BB];
__device__ float g_g0p[6 * 4 * HH * BB];   // layer0 gate partials: 3 pieces x ksplit2, [p][row][b]
__device__ float g_g1p[4 * 4 * HH * BB];   // layer1: 2 pieces x ksplit2
__device__ float g_qp[8 * HH * BB];        // q: 1 piece x ksplit8
__device__ float g_pop[8 * HH * BB];       // pre-output: 2 pieces x ksplit4

struct Piece { const float* W; const float* X; int ldw; int col; };

// ---------------- embedding gather + transpose ----------------
// grid: T * (E/32) blocks; block handles one t and a 32-wide e-tile for all 32 b.
__global__ void embed_kernel(const int* __restrict__ ids, const float* __restrict__ emb) {
    __shared__ float sh[32][33];
    int t = blockIdx.x >> 5;
    int etile = (blockIdx.x & 31) * 32;
    int w = threadIdx.x >> 5, lane = threadIdx.x & 31;
    #pragma unroll
    for (int i = 0; i < 4; i++) {
        int b = w + i * 8;
        int id = ids[t * BB + b];
        sh[b][lane] = emb[(size_t)id * EE + etile + lane];   // coalesced read
    }
    __syncthreads();
    #pragma unroll
    for (int i = 0; i < 4; i++) {
        int e = w + i * 8;
        g_embT[((size_t)t * EE + etile + e) * BB + lane] = sh[lane][e];  // coalesced write
    }
}

__global__ void init_kernel(const float* __restrict__ h0in, const float* __restrict__ c0in) {
    int idx = blockIdx.x * 256 + threadIdx.x;
    if (idx < BB * HH) {
        int b = idx >> 10, hh = idx & 1023;
        int tr = hh * BB + b;
        g_h0T[tr] = h0in[idx];
        g_h1T[tr] = h0in[BB * HH + idx];
        g_c0T[tr] = c0in[idx];
        g_c1T[tr] = c0in[BB * HH + idx];
        g_feedT[tr] = 0.f;
    }
}

// ---------------- fp32 register-tiled GEMM ----------------
// out[pidx][row][b] = sum_k W[row][col+k] * X[k][b]   (partials, reduced later)
// grid: (M/64, nPieces, kSplit), 128 threads. Thread: 4 rows x 4 batches.
__global__ void __launch_bounds__(128, 4)
gemm2_kernel(Piece p0, Piece p1, Piece p2, float* __restrict__ out, int M) {
    Piece p = p0;
    if (blockIdx.y == 1) p = p1;
    else if (blockIdx.y == 2) p = p2;
    const int kChunk = 1024 / gridDim.z;
    const int kbase  = blockIdx.z * kChunk;
    const int pidx   = blockIdx.y * gridDim.z + blockIdx.z;

    __shared__ float Ws[64][132];   // [row][k], pad for bank spread, float4-aligned
    __shared__ float xs[128][36];   // [k][b],  pad 36 (float4-aligned)

    int tid = threadIdx.x;
    int rt = tid >> 3;              // 0..15 -> 4 rows each
    int bt = tid & 7;               // 0..7  -> 4 batches each
    int rowBase = blockIdx.x * 64;

    const float* Wbase = p.W + (size_t)rowBase * p.ldw + p.col + kbase;
    const float* X     = p.X + (size_t)kbase * BB;

    float acc[4][4];
    #pragma unroll
    for (int i = 0; i < 4; i++)
        #pragma unroll
        for (int j = 0; j < 4; j++) acc[i][j] = 0.f;

    for (int kt = 0; kt < kChunk; kt += 128) {
        // load W chunk: 64 rows x 128 k (coalesced float4 per row)
        #pragma unroll
        for (int i = 0; i < 16; i++) {
            int f4 = tid + i * 128;
            int row = f4 >> 5, kq = f4 & 31;
            float4 w = __ldg((const float4*)(Wbase + (size_t)row * p.ldw + kt + kq * 4));
            *(float4*)&Ws[row][kq * 4] = w;
        }
        // load x chunk: 128 k x 32 b (fully coalesced float4)
        #pragma unroll
        for (int i = 0; i < 8; i++) {
            int f4 = tid + i * 128;
            int k = f4 >> 3, bq = f4 & 7;
            float4 v = __ldg((const float4*)(X + (size_t)(kt + k) * BB + bq * 4));
            *(float4*)&xs[k][bq * 4] = v;
        }
        __syncthreads();

        #pragma unroll 4
        for (int kq = 0; kq < 32; kq++) {
            float4 xv0 = *(const float4*)&xs[kq * 4 + 0][bt * 4];
            float4 xv1 = *(const float4*)&xs[kq * 4 + 1][bt * 4];
            float4 xv2 = *(const float4*)&xs[kq * 4 + 2][bt * 4];
            float4 xv3 = *(const float4*)&xs[kq * 4 + 3][bt * 4];
            #pragma unroll
            for (int i = 0; i < 4; i++) {
                float4 w = *(const float4*)&Ws[rt * 4 + i][kq * 4];
                acc[i][0] = fmaf(w.x, xv0.x, acc[i][0]);
                acc[i][0] = fmaf(w.y, xv1.x, acc[i][0]);
                acc[i][0] = fmaf(w.z, xv2.x, acc[i][0]);
                acc[i][0] = fmaf(w.w, xv3.x, acc[i][0]);
                acc[i][1] = fmaf(w.x, xv0.y, acc[i][1]);
                acc[i][1] = fmaf(w.y, xv1.y, acc[i][1]);
                acc[i][1] = fmaf(w.z, xv2.y, acc[i][1]);
                acc[i][1] = fmaf(w.w, xv3.y, acc[i][1]);
                acc[i][2] = fmaf(w.x, xv0.z, acc[i][2]);
                acc[i][2] = fmaf(w.y, xv1.z, acc[i][2]);
                acc[i][2] = fmaf(w.z, xv2.z, acc[i][2]);
                acc[i][2] = fmaf(w.w, xv3.z, acc[i][2]);
                acc[i][3] = fmaf(w.x, xv0.w, acc[i][3]);
                acc[i][3] = fmaf(w.y, xv1.w, acc[i][3]);
                acc[i][3] = fmaf(w.z, xv2.w, acc[i][3]);
                acc[i][3] = fmaf(w.w, xv3.w, acc[i][3]);
            }
        }
        __syncthreads();
    }

    float* o = out + (size_t)pidx * M * BB;
    #pragma unroll
    for (int i = 0; i < 4; i++) {
        int row = rowBase + rt * 4 + i;
        *(float4*)&o[(size_t)row * BB + bt * 4] =
            make_float4(acc[i][0], acc[i][1], acc[i][2], acc[i][3]);
    }
}

__device__ __forceinline__ float sigm(float x) { return 1.f / (1.f + expf(-x)); }

// ---------------- LSTM cell pointwise; partials layout [p][row][b] ----------------
__global__ void cell_kernel(const float* __restrict__ gp, int np,
                            const float* __restrict__ b_ih, const float* __restrict__ b_hh,
                            float* __restrict__ hT, float* __restrict__ cT) {
    int idx = blockIdx.x * 256 + threadIdx.x;
    if (idx >= BB * HH) return;
    int hh = idx >> 5, b = idx & 31;
    float gi = 0.f, gf = 0.f, gg = 0.f, go = 0.f;
    for (int p = 0; p < np; p++) {
        const float* g = gp + (size_t)p * 4 * HH * BB;
        gi += g[(size_t)hh * BB + b];
        gf += g[(size_t)(HH + hh) * BB + b];
        gg += g[(size_t)(2 * HH + hh) * BB + b];
        go += g[(size_t)(3 * HH + hh) * BB + b];
    }
    gi += b_ih[hh]          + b_hh[hh];
    gf += b_ih[HH + hh]     + b_hh[HH + hh];
    gg += b_ih[2 * HH + hh] + b_hh[2 * HH + hh];
    go += b_ih[3 * HH + hh] + b_hh[3 * HH + hh];
    float cn = sigm(gf) * cT[idx] + sigm(gi) * tanhf(gg);
    cT[idx] = cn;
    hT[idx] = sigm(go) * tanhf(cn);
}

// ---------------- attention: scores + masked softmax + context vector ----------------
__global__ void attn_kernel(const float* __restrict__ ctx, const int* __restrict__ lens,
                            float* __restrict__ attn_out, int t) {
    int b = blockIdx.x;
    int tid = threadIdx.x;
    __shared__ float qs[HH];
    __shared__ float sc[SS];

    for (int i = tid; i < HH; i += 256) {
        float s = 0.f;
        #pragma unroll
        for (int p = 0; p < 8; p++)
            s += g_qp[((size_t)p * HH + i) * BB + b];
        qs[i] = s;
    }
    __syncthreads();

    int w = tid >> 5, lane = tid & 31;       // 8 warps, each handles 8 s-values
    #pragma unroll
    for (int si = 0; si < 8; si++) {
        int s = si * 8 + w;
        const float* cr = ctx + ((size_t)s * BB + b) * HH;   // context[s,b,:]
        float sum = 0.f;
        for (int i = lane; i < HH; i += 32) sum = fmaf(qs[i], cr[i], sum);
        #pragma unroll
        for (int o = 16; o > 0; o >>= 1) sum += __shfl_xor_sync(0xffffffffu, sum, o);
        if (lane == 0) sc[s] = sum;
    }
    __syncthreads();

    if (tid == 0) {
        int len = lens[b];
        len = len < 1 ? 1 : (len > SS ? SS : len);
        float m = sc[0];
        for (int s = 1; s < len; s++) m = fmaxf(m, sc[s]);
        float sum = 0.f;
        for (int s = 0; s < len; s++) { float e = expf(sc[s] - m); sc[s] = e; sum += e; }
        float inv = 1.f / sum;
        for (int s = 0; s < len; s++) sc[s] *= inv;
        for (int s = len; s < SS; s++) sc[s] = 0.f;
    }
    __syncthreads();

    if (tid < SS) attn_out[((size_t)t * BB + b) * SS + tid] = sc[tid];

    float a0 = 0.f, a1 = 0.f, a2 = 0.f, a3 = 0.f;
    for (int s = 0; s < SS; s++) {
        float a = sc[s];
        const float* cr = ctx + ((size_t)s * BB + b) * HH;
        a0 = fmaf(a, cr[tid      ], a0);
        a1 = fmaf(a, cr[tid + 256], a1);
        a2 = fmaf(a, cr[tid + 512], a2);
        a3 = fmaf(a, cr[tid + 768], a3);
    }
    g_cvecT[(size_t)(tid      ) * BB + b] = a0;
    g_cvecT[(size_t)(tid + 256) * BB + b] = a1;
    g_cvecT[(size_t)(tid + 512) * BB + b] = a2;
    g_cvecT[(size_t)(tid + 768) * BB + b] = a3;
}

// ---------------- output epilogue: reduce 8 partials, tanh, write output + feed ----------------
__global__ void outepi_kernel(float* __restrict__ outv, int t) {
    int idx = blockIdx.x * 256 + threadIdx.x;
    if (idx >= BB * HH) return;
    int hh = idx >> 5, b = idx & 31;
    float v = 0.f;
    #pragma unroll
    for (int p = 0; p < 8; p++)
        v += g_pop[(size_t)p * HH * BB + idx];
    v = tanhf(v);
    outv[((size_t)t * BB + b) * HH + hh] = v;
    g_feedT[idx] = v;
}

// ---------------- launcher (graph-capturable: kernel launches only) ----------------
extern "C" void kernel_launch(void* const* d_in, const int* in_sizes, int n_in,
                              void* d_out, int out_size) {
    const int*   ids   = (const int*)  d_in[0];
    const float* ctx   = (const float*)d_in[1];
    const int*   lens  = (const int*)  d_in[2];
    const float* h0    = (const float*)d_in[3];
    const float* c0    = (const float*)d_in[4];
    const float* emb   = (const float*)d_in[5];
    const float* W_ih0 = (const float*)d_in[6];
    const float* W_hh0 = (const float*)d_in[7];
    const float* b_ih0 = (const float*)d_in[8];
    const float* b_hh0 = (const float*)d_in[9];
    const float* W_ih1 = (const float*)d_in[10];
    const float* W_hh1 = (const float*)d_in[11];
    const float* b_ih1 = (const float*)d_in[12];
    const float* b_hh1 = (const float*)d_in[13];
    const float* W_in  = (const float*)d_in[14];
    const float* W_out = (const float*)d_in[15];

    float* outv = (float*)d_out;                       // outputs [T,B,H]
    float* attn = outv + (size_t)TT * BB * HH;         // attns   [T,B,S]

    float *p_embT, *p_h0T, *p_h1T, *p_feedT, *p_cvecT, *p_g0, *p_g1, *p_q, *p_po, *p_c0T, *p_c1T;
    cudaGetSymbolAddress((void**)&p_embT,  g_embT);
    cudaGetSymbolAddress((void**)&p_h0T,   g_h0T);
    cudaGetSymbolAddress((void**)&p_h1T,   g_h1T);
    cudaGetSymbolAddress((void**)&p_c0T,   g_c0T);
    cudaGetSymbolAddress((void**)&p_c1T,   g_c1T);
    cudaGetSymbolAddress((void**)&p_feedT, g_feedT);
    cudaGetSymbolAddress((void**)&p_cvecT, g_cvecT);
    cudaGetSymbolAddress((void**)&p_g0,    g_g0p);
    cudaGetSymbolAddress((void**)&p_g1,    g_g1p);
    cudaGetSymbolAddress((void**)&p_q,     g_qp);
    cudaGetSymbolAddress((void**)&p_po,    g_pop);

    embed_kernel<<<TT * (EE / 32), 256>>>(ids, emb);
    init_kernel<<<(BB * HH + 255) / 256, 256>>>(h0, c0);

    for (int t = 0; t < TT; t++) {
        // layer 0 gates: W_ih0[:, :E] @ emb_t + W_ih0[:, E:] @ feed + W_hh0 @ h0
        Piece q0{W_ih0, p_embT + (size_t)t * EE * BB, 2 * HH, 0};
        Piece q1{W_ih0, p_feedT, 2 * HH, HH};
        Piece q2{W_hh0, p_h0T, HH, 0};
        gemm2_kernel<<<dim3(4 * HH / 64, 3, 2), 128>>>(q0, q1, q2, p_g0, 4 * HH);
        cell_kernel<<<(BB * HH + 255) / 256, 256>>>(p_g0, 6, b_ih0, b_hh0, p_h0T, p_c0T);

        // layer 1 gates: W_ih1 @ h0_new + W_hh1 @ h1_prev
        Piece r0{W_ih1, p_h0T, HH, 0};
        Piece r1{W_hh1, p_h1T, HH, 0};
        gemm2_kernel<<<dim3(4 * HH / 64, 2, 2), 128>>>(r0, r1, r1, p_g1, 4 * HH);
        cell_kernel<<<(BB * HH + 255) / 256, 256>>>(p_g1, 4, b_ih1, b_hh1, p_h1T, p_c1T);

        // q = W_in @ h1   (K split 8 for occupancy: 128 blocks)
        Piece s0{W_in, p_h1T, HH, 0};
        gemm2_kernel<<<dim3(HH / 64, 1, 8), 128>>>(s0, s0, s0, p_q, HH);

        attn_kernel<<<BB, 256>>>(ctx, lens, attn, t);

        // pre-output = W_out[:, :H] @ c_vec + W_out[:, H:] @ h1  (2 pieces x K split 4)
        Piece u0{W_out, p_cvecT, 2 * HH, 0};
        Piece u1{W_out, p_h1T, 2 * HH, HH};
        gemm2_kernel<<<dim3(HH / 64, 2, 4), 128>>>(u0, u1, u1, p_po, HH);

        outepi_kernel<<<(BB * HH + 255) / 256, 256>>>(outv, t);
    }
}

// round 8
// speedup vs baseline: 2.9171x; 1.2020x over previous
#include <cuda_runtime.h>
#include <cuda_bf16.h>
#include <math.h>
#include <stdint.h>

#define TT 64
#define BB 32
#define SS 64
#define HH 1024

typedef __nv_bfloat16 bf16;

// ---------------- static device scratch (no allocations) ----------------
// Weight fragments (uint32): [rowtile16][kstep][sel hi/lo][lane(32)][reg(4)]
__device__ uint32_t g_w0[(size_t)256 * 192 * 2 * 128];  // gates0: ks 0-127 = W_ih0, 128-191 = W_hh0
__device__ uint32_t g_w1[(size_t)256 * 128 * 2 * 128];  // gates1: ks 0-63 = W_ih1, 64-127 = W_hh1
__device__ uint32_t g_wq[(size_t)64 * 64 * 2 * 128];    // q: W_in
__device__ uint32_t g_wo[(size_t)64 * 128 * 2 * 128];   // out: W_out (ks 0-63 cvec, 64-127 h1)

// Activation B-fragments (uint32): per 1024-k vector: [kstep(64)][sel(2)][ntile(4)][lane(32)][reg(2)]
__device__ uint32_t g_embx[(size_t)TT * 32768];
__device__ uint32_t g_h0x[32768];
__device__ uint32_t g_h1x[32768];
__device__ uint32_t g_feedx[32768];
__device__ uint32_t g_cvx[32768];

__device__ float g_c0T[HH * BB];                 // [hh][b]
__device__ float g_c1T[HH * BB];
__device__ float g_p0[(size_t)8 * 4 * HH * BB];  // gates partials [p=8][4H][32]
__device__ float g_p1[(size_t)8 * 4 * HH * BB];
__device__ float g_pq[(size_t)16 * HH * BB];     // [p=16][H][32]
__device__ float g_po[(size_t)16 * HH * BB];
__device__ unsigned g_sync[4 * TT];

// ---------------- helpers ----------------
__device__ __forceinline__ float sigm(float x) { return 1.f / (1.f + expf(-x)); }

// Store activation value into hi/lo B-fragment layout.
__device__ __forceinline__ void store_x(bf16* base, int hh, int b, float v) {
    int kstep = hh >> 4, kk = hh & 15;
    int ntile = b >> 3, gid = b & 7;
    int reg = kk >> 3, krem = kk & 7, tig = krem >> 1, half = krem & 1;
    int lane = gid * 4 + tig;
    bf16 hi = __float2bfloat16(v);
    bf16 lo = __float2bfloat16(v - __bfloat162float(hi));
    size_t i0 = ((((size_t)kstep * 2 + 0) * 4 + ntile) * 64 + lane * 2 + reg) * 2 + half;
    size_t i1 = ((((size_t)kstep * 2 + 1) * 4 + ntile) * 64 + lane * 2 + reg) * 2 + half;
    base[i0] = hi;
    base[i1] = lo;
}

__device__ __forceinline__ void mma_bf16(float* d, const uint32_t* a, uint32_t b0, uint32_t b1) {
    asm volatile(
        "mma.sync.aligned.m16n8k16.row.col.f32.bf16.bf16.f32 "
        "{%0,%1,%2,%3}, {%4,%5,%6,%7}, {%8,%9}, {%0,%1,%2,%3};"
        : "+f"(d[0]), "+f"(d[1]), "+f"(d[2]), "+f"(d[3])
        : "r"(a[0]), "r"(a[1]), "r"(a[2]), "r"(a[3]), "r"(b0), "r"(b1));
}

struct GP {
    const uint32_t* Wt;
    const uint32_t* x0; const uint32_t* x1; const uint32_t* x2;
    float* part;
    int nk;        // total ksteps
    int kspb;      // ksteps per block (gridDim.y = nk/kspb)
    unsigned* ctr;
    unsigned nb;
};

// ---------------- HMMA GEMM core: block = 256 rows (4 warps x 64), N=32 ----------------
__device__ __forceinline__ void gemm_core(const GP& g) {
    int tid = threadIdx.x, wid = tid >> 5, lane = tid & 31;
    int mtile = blockIdx.x, z = blockIdx.y;
    int ks0 = z * g.kspb;

    float acc[4][4][4];
    #pragma unroll
    for (int i = 0; i < 4; i++)
        #pragma unroll
        for (int nt = 0; nt < 4; nt++)
            #pragma unroll
            for (int r = 0; r < 4; r++) acc[i][nt][r] = 0.f;

    const uint4* Ah[4];
    const uint4* Al[4];
    #pragma unroll
    for (int i = 0; i < 4; i++) {
        size_t rt = (size_t)mtile * 16 + wid * 4 + i;
        Ah[i] = (const uint4*)(g.Wt + ((rt * g.nk + ks0) * 2 + 0) * 128) + lane;
        Al[i] = (const uint4*)(g.Wt + ((rt * g.nk + ks0) * 2 + 1) * 128) + lane;
    }

    for (int s = 0; s < g.kspb; s++) {
        int ks = ks0 + s;
        const uint32_t* xsrc = (ks < 64) ? g.x0 : ((ks < 128) ? g.x1 : g.x2);
        const uint2* xb = (const uint2*)(xsrc + (size_t)(ks & 63) * 512);

        uint2 bh[4], bl[4];
        #pragma unroll
        for (int nt = 0; nt < 4; nt++) {
            bh[nt] = __ldg(&xb[nt * 32 + lane]);
            bl[nt] = __ldg(&xb[128 + nt * 32 + lane]);
        }
        uint4 ah[4], al[4];
        #pragma unroll
        for (int i = 0; i < 4; i++) {
            ah[i] = __ldg(Ah[i]);
            al[i] = __ldg(Al[i]);
            Ah[i] += 64;
            Al[i] += 64;
        }
        #pragma unroll
        for (int i = 0; i < 4; i++) {
            #pragma unroll
            for (int nt = 0; nt < 4; nt++) {
                mma_bf16(acc[i][nt], (const uint32_t*)&ah[i], bh[nt].x, bh[nt].y);
                mma_bf16(acc[i][nt], (const uint32_t*)&ah[i], bl[nt].x, bl[nt].y);
                mma_bf16(acc[i][nt], (const uint32_t*)&al[i], bh[nt].x, bh[nt].y);
            }
        }
    }

    // write partials: D frag: d0,d1 = (row gid, col 2tig..+1); d2,d3 = row gid+8
    int gid = lane >> 2, tig = lane & 3;
    int M = gridDim.x * 256;
    float* base = g.part + (size_t)z * M * 32;
    #pragma unroll
    for (int i = 0; i < 4; i++) {
        int row0 = (mtile * 16 + wid * 4 + i) * 16 + gid;
        #pragma unroll
        for (int nt = 0; nt < 4; nt++) {
            int col = nt * 8 + tig * 2;
            *(float2*)&base[(size_t)row0 * 32 + col] = make_float2(acc[i][nt][0], acc[i][nt][1]);
            *(float2*)&base[(size_t)(row0 + 8) * 32 + col] = make_float2(acc[i][nt][2], acc[i][nt][3]);
        }
    }
    __threadfence();
    __syncthreads();
    if (tid == 0) atomicAdd(g.ctr, 1u);
}

__device__ __forceinline__ void spin_all(unsigned* ctr, unsigned nb) {
    if (threadIdx.x == 0)
        while (*(volatile unsigned*)ctr < nb) __nanosleep(64);
    __syncthreads();
    __threadfence();
}

// ---------------- fused GEMM + LSTM cell (gates0 / gates1) ----------------
__global__ void __launch_bounds__(128, 1)
k_cellgemm(GP g, const float* __restrict__ bih, const float* __restrict__ bhh,
           float* __restrict__ cT, bf16* __restrict__ hx) {
    gemm_core(g);
    spin_all(g.ctr, g.nb);

    int lin = blockIdx.y * gridDim.x + blockIdx.x;   // 0..127
    #pragma unroll
    for (int j = 0; j < 2; j++) {
        int e = lin * 256 + j * 128 + threadIdx.x;   // e = hh*32 + b, over H*32 = 32768
        int hh = e >> 5, b = e & 31;
        float gi = 0.f, gf = 0.f, gg = 0.f, go = 0.f;
        #pragma unroll
        for (int p = 0; p < 8; p++) {
            const float* gp = g.part + (size_t)p * 131072;
            gi += __ldcg(&gp[e]);
            gf += __ldcg(&gp[e + 32768]);
            gg += __ldcg(&gp[e + 65536]);
            go += __ldcg(&gp[e + 98304]);
        }
        gi += bih[hh] + bhh[hh];
        gf += bih[HH + hh] + bhh[HH + hh];
        gg += bih[2 * HH + hh] + bhh[2 * HH + hh];
        go += bih[3 * HH + hh] + bhh[3 * HH + hh];
        float cn = sigm(gf) * cT[e] + sigm(gi) * tanhf(gg);
        cT[e] = cn;
        float h = sigm(go) * tanhf(cn);
        store_x(hx, hh, b, h);
    }
}

// ---------------- fused q-GEMM + attention ----------------
__global__ void __launch_bounds__(128, 1)
k_qattn(GP g, const float* __restrict__ ctx, const int* __restrict__ lens,
        float* __restrict__ attn_out, int t) {
    gemm_core(g);
    int lin = blockIdx.y * gridDim.x + blockIdx.x;   // 0..63
    if (lin >= 32) return;
    spin_all(g.ctr, g.nb);

    int b = lin;
    int tid = threadIdx.x, wid = tid >> 5, lane = tid & 31;
    __shared__ float qs[HH];
    __shared__ float sc[SS];

    for (int i = tid; i < HH; i += 128) {
        float s = 0.f;
        #pragma unroll
        for (int p = 0; p < 16; p++)
            s += __ldcg(&g_pq[(size_t)p * 32768 + (size_t)i * 32 + b]);
        qs[i] = s;
    }
    __syncthreads();

    #pragma unroll
    for (int si = 0; si < 16; si++) {
        int s = wid * 16 + si;
        const float* cr = ctx + ((size_t)s * BB + b) * HH;
        float sum = 0.f;
        for (int i = lane; i < HH; i += 32) sum = fmaf(qs[i], __ldg(&cr[i]), sum);
        #pragma unroll
        for (int o = 16; o > 0; o >>= 1) sum += __shfl_xor_sync(0xffffffffu, sum, o);
        if (lane == 0) sc[s] = sum;
    }
    __syncthreads();

    if (tid == 0) {
        int len = lens[b];
        len = len < 1 ? 1 : (len > SS ? SS : len);
        float m = sc[0];
        for (int s = 1; s < len; s++) m = fmaxf(m, sc[s]);
        float sum = 0.f;
        for (int s = 0; s < len; s++) { float e = expf(sc[s] - m); sc[s] = e; sum += e; }
        float inv = 1.f / sum;
        for (int s = 0; s < len; s++) sc[s] *= inv;
        for (int s = len; s < SS; s++) sc[s] = 0.f;
    }
    __syncthreads();

    if (tid < SS) attn_out[((size_t)t * BB + b) * SS + tid] = sc[tid];

    #pragma unroll
    for (int j = 0; j < 8; j++) {
        int hh = tid + j * 128;
        float acc = 0.f;
        for (int s = 0; s < SS; s++)
            acc = fmaf(sc[s], __ldg(&ctx[((size_t)s * BB + b) * HH + hh]), acc);
        store_x((bf16*)g_cvx, hh, b, acc);
    }
}

// ---------------- fused out-GEMM + epilogue ----------------
__global__ void __launch_bounds__(128, 1)
k_out(GP g, float* __restrict__ outv, int t) {
    gemm_core(g);
    spin_all(g.ctr, g.nb);

    int lin = blockIdx.y * gridDim.x + blockIdx.x;   // 0..63
    #pragma unroll
    for (int j = 0; j < 4; j++) {
        int e = lin * 512 + j * 128 + threadIdx.x;   // over H*32 = 32768
        int hh = e >> 5, b = e & 31;
        float v = 0.f;
        #pragma unroll
        for (int p = 0; p < 16; p++)
            v += __ldcg(&g_po[(size_t)p * 32768 + e]);
        v = tanhf(v);
        outv[((size_t)t * BB + b) * HH + hh] = v;
        store_x((bf16*)g_feedx, hh, b, v);
    }
}

// ---------------- weight conversion: fp32 -> hi/lo A-fragments ----------------
__global__ void k_wconv(const float* __restrict__ W, int ldw,
                        uint32_t* __restrict__ dst, int nkTot, int ksBase) {
    int rt = blockIdx.x, ks = blockIdx.y;
    int lane = threadIdx.x;
    int gid = lane >> 2, tig = lane & 3;
    uint32_t hi[4], lo[4];
    #pragma unroll
    for (int r = 0; r < 4; r++) {
        int row = rt * 16 + gid + (r & 1) * 8;
        int kk = ks * 16 + (r >> 1) * 8 + tig * 2;
        float w0 = __ldg(&W[(size_t)row * ldw + kk]);
        float w1 = __ldg(&W[(size_t)row * ldw + kk + 1]);
        bf16 h0 = __float2bfloat16(w0), h1 = __float2bfloat16(w1);
        bf16 l0 = __float2bfloat16(w0 - __bfloat162float(h0));
        bf16 l1 = __float2bfloat16(w1 - __bfloat162float(h1));
        hi[r] = ((uint32_t)__bfloat16_as_ushort(h1) << 16) | __bfloat16_as_ushort(h0);
        lo[r] = ((uint32_t)__bfloat16_as_ushort(l1) << 16) | __bfloat16_as_ushort(l0);
    }
    size_t bi = (((size_t)rt * nkTot + ksBase + ks) * 2) * 128 + lane * 4;
    #pragma unroll
    for (int r = 0; r < 4; r++) {
        dst[bi + r] = hi[r];
        dst[bi + 128 + r] = lo[r];
    }
}

// ---------------- embedding gather -> B-fragments ----------------
__global__ void k_embx(const int* __restrict__ ids, const float* __restrict__ emb) {
    int t = blockIdx.x;
    int tid = threadIdx.x;
    int b = tid & 31;
    int id = ids[t * BB + b];
    bf16* dstx = (bf16*)(g_embx + (size_t)t * 32768);
    const float* src = emb + (size_t)id * HH;
    for (int hh = tid >> 5; hh < HH; hh += 8)
        store_x(dstx, hh, b, __ldg(&src[hh]));
}

// ---------------- init ----------------
__global__ void k_init(const float* __restrict__ h0, const float* __restrict__ c0) {
    int idx = blockIdx.x * 256 + threadIdx.x;
    if (idx < 4 * TT) g_sync[idx] = 0u;
    if (idx >= HH * BB) return;
    int hh = idx >> 5, b = idx & 31;
    g_c0T[idx] = c0[(size_t)(0 * BB + b) * HH + hh];
    g_c1T[idx] = c0[(size_t)(1 * BB + b) * HH + hh];
    store_x((bf16*)g_h0x, hh, b, h0[(size_t)(0 * BB + b) * HH + hh]);
    store_x((bf16*)g_h1x, hh, b, h0[(size_t)(1 * BB + b) * HH + hh]);
    store_x((bf16*)g_feedx, hh, b, 0.f);
}

// ---------------- launcher (graph-capturable: kernel launches only) ----------------
extern "C" void kernel_launch(void* const* d_in, const int* in_sizes, int n_in,
                              void* d_out, int out_size) {
    const int*   ids   = (const int*)  d_in[0];
    const float* ctx   = (const float*)d_in[1];
    const int*   lens  = (const int*)  d_in[2];
    const float* h0    = (const float*)d_in[3];
    const float* c0    = (const float*)d_in[4];
    const float* emb   = (const float*)d_in[5];
    const float* W_ih0 = (const float*)d_in[6];
    const float* W_hh0 = (const float*)d_in[7];
    const float* b_ih0 = (const float*)d_in[8];
    const float* b_hh0 = (const float*)d_in[9];
    const float* W_ih1 = (const float*)d_in[10];
    const float* W_hh1 = (const float*)d_in[11];
    const float* b_ih1 = (const float*)d_in[12];
    const float* b_hh1 = (const float*)d_in[13];
    const float* W_in  = (const float*)d_in[14];
    const float* W_out = (const float*)d_in[15];

    float* outv = (float*)d_out;                      // outputs [T,B,H]
    float* attn = outv + (size_t)TT * BB * HH;        // attns   [T,B,S]

    uint32_t *p_w0, *p_w1, *p_wq, *p_wo, *p_embx, *p_h0x, *p_h1x, *p_feedx, *p_cvx;
    float *p_c0T, *p_c1T, *p_p0, *p_p1, *p_pq, *p_po;
    unsigned* p_sync;
    cudaGetSymbolAddress((void**)&p_w0,    g_w0);
    cudaGetSymbolAddress((void**)&p_w1,    g_w1);
    cudaGetSymbolAddress((void**)&p_wq,    g_wq);
    cudaGetSymbolAddress((void**)&p_wo,    g_wo);
    cudaGetSymbolAddress((void**)&p_embx,  g_embx);
    cudaGetSymbolAddress((void**)&p_h0x,   g_h0x);
    cudaGetSymbolAddress((void**)&p_h1x,   g_h1x);
    cudaGetSymbolAddress((void**)&p_feedx, g_feedx);
    cudaGetSymbolAddress((void**)&p_cvx,   g_cvx);
    cudaGetSymbolAddress((void**)&p_c0T,   g_c0T);
    cudaGetSymbolAddress((void**)&p_c1T,   g_c1T);
    cudaGetSymbolAddress((void**)&p_p0,    g_p0);
    cudaGetSymbolAddress((void**)&p_p1,    g_p1);
    cudaGetSymbolAddress((void**)&p_pq,    g_pq);
    cudaGetSymbolAddress((void**)&p_po,    g_po);
    cudaGetSymbolAddress((void**)&p_sync,  g_sync);

    // One-time conversions (deterministic; re-run every replay)
    k_wconv<<<dim3(256, 128), 32>>>(W_ih0, 2048, p_w0, 192, 0);
    k_wconv<<<dim3(256, 64),  32>>>(W_hh0, 1024, p_w0, 192, 128);
    k_wconv<<<dim3(256, 64),  32>>>(W_ih1, 1024, p_w1, 128, 0);
    k_wconv<<<dim3(256, 64),  32>>>(W_hh1, 1024, p_w1, 128, 64);
    k_wconv<<<dim3(64, 64),   32>>>(W_in,  1024, p_wq, 64, 0);
    k_wconv<<<dim3(64, 128),  32>>>(W_out, 2048, p_wo, 128, 0);
    k_embx<<<TT, 256>>>(ids, emb);
    k_init<<<128, 256>>>(h0, c0);

    for (int t = 0; t < TT; t++) {
        // gates0: M=4096, K=3072 (ks 0-63 emb_t, 64-127 feed, 128-191 h0); grid(16,8)=128 blocks
        GP a0{p_w0, p_embx + (size_t)t * 32768, p_feedx, p_h0x,
              p_p0, 192, 24, p_sync + 4 * t + 0, 128};
        k_cellgemm<<<dim3(16, 8), 128>>>(a0, b_ih0, b_hh0, p_c0T, (bf16*)p_h0x);

        // gates1: M=4096, K=2048 (ks 0-63 h0_new, 64-127 h1_prev)
        GP a1{p_w1, p_h0x, p_h1x, nullptr, p_p1, 128, 16, p_sync + 4 * t + 1, 128};
        k_cellgemm<<<dim3(16, 8), 128>>>(a1, b_ih1, b_hh1, p_c1T, (bf16*)p_h1x);

        // q = W_in @ h1: M=1024, K=1024; grid(4,16)=64 blocks; blocks 0-31 run attention tail
        GP aq{p_wq, p_h1x, nullptr, nullptr, p_pq, 64, 4, p_sync + 4 * t + 2, 64};
        k_qattn<<<dim3(4, 16), 128>>>(aq, ctx, lens, attn, t);

        // pre-output: M=1024, K=2048 (ks 0-63 c_vec, 64-127 h1)
        GP ao{p_wo, p_cvx, p_h1x, nullptr, p_po, 128, 8, p_sync + 4 * t + 3, 64};
        k_out<<<dim3(4, 16), 128>>>(ao, outv, t);
    }
}

// round 10
// speedup vs baseline: 4.5034x; 1.5438x over previous
#include <cuda_runtime.h>
#include <cuda_bf16.h>
#include <math.h>
#include <stdint.h>

#define TT 64
#define BB 32
#define SS 64
#define HH 1024
#define NBLK 128

typedef __nv_bfloat16 bf16;

// ---------------- static device scratch (no allocations) ----------------
// Weight fragments (uint32): [rowtile16][kstep][sel hi/lo][lane(32)][reg(4)]
// gates matrices use GATE-PERMUTED row order (see k_wconv).
__device__ uint32_t g_w0[(size_t)256 * 192 * 2 * 128];  // gates0: ks 0-127 W_ih0, 128-191 W_hh0
__device__ uint32_t g_w1[(size_t)256 * 128 * 2 * 128];  // gates1: ks 0-63 W_ih1, 64-127 W_hh1
__device__ uint32_t g_wq[(size_t)64 * 64 * 2 * 128];    // q: W_in
__device__ uint32_t g_wo[(size_t)64 * 128 * 2 * 128];   // out: W_out (ks 0-63 cvec, 64-127 h1)

// Activation B-fragments: per 1024-k vector: [kstep(64)][sel(2)][ntile(4)][lane(32)][reg(2)]
// h0x/h1x DOUBLE-BUFFERED: a same-phase GEMM reads the whole old buffer while each block
// writes its slice of the new one (this was the R9 race).
__device__ uint32_t g_embx[(size_t)TT * 32768];
__device__ uint32_t g_h0x[2][32768];
__device__ uint32_t g_h1x[2][32768];
__device__ uint32_t g_feedx[32768];
__device__ uint32_t g_cvx[32768];

__device__ float g_c0T[HH * BB];      // [hh][b]
__device__ float g_c1T[HH * BB];
__device__ float g_qf[HH * BB];       // q final, [b][row] (transposed for attn reads)
__device__ float g_po[HH * BB];       // out-GEMM h1-half, [row][b]
__device__ unsigned g_count;
__device__ volatile unsigned g_sense;

// ---------------- helpers ----------------
__device__ __forceinline__ float sigm(float x) { return 1.f / (1.f + expf(-x)); }

// Store activation value into hi/lo B-fragment layout.
__device__ __forceinline__ void store_x(bf16* base, int hh, int b, float v) {
    int kstep = hh >> 4, kk = hh & 15;
    int ntile = b >> 3, gid = b & 7;
    int reg = kk >> 3, krem = kk & 7, tig = krem >> 1, half = krem & 1;
    int lane = gid * 4 + tig;
    bf16 hi = __float2bfloat16(v);
    bf16 lo = __float2bfloat16(v - __bfloat162float(hi));
    size_t i0 = ((((size_t)kstep * 2 + 0) * 4 + ntile) * 64 + lane * 2 + reg) * 2 + half;
    size_t i1 = ((((size_t)kstep * 2 + 1) * 4 + ntile) * 64 + lane * 2 + reg) * 2 + half;
    base[i0] = hi;
    base[i1] = lo;
}

__device__ __forceinline__ void mma_bf16(float* d, const uint32_t* a, uint32_t b0, uint32_t b1) {
    asm volatile(
        "mma.sync.aligned.m16n8k16.row.col.f32.bf16.bf16.f32 "
        "{%0,%1,%2,%3}, {%4,%5,%6,%7}, {%8,%9}, {%0,%1,%2,%3};"
        : "+f"(d[0]), "+f"(d[1]), "+f"(d[2]), "+f"(d[3])
        : "r"(a[0]), "r"(a[1]), "r"(a[2]), "r"(a[3]), "r"(b0), "r"(b1));
}

// device-wide sense-reversing barrier (all NBLK blocks co-resident)
__device__ __forceinline__ void gbar(unsigned* sense) {
    __syncthreads();
    if (threadIdx.x == 0) {
        unsigned s = *sense ^ 1u;
        __threadfence();
        if (atomicAdd(&g_count, 1u) == (unsigned)(gridDim.x - 1)) {
            g_count = 0u;
            __threadfence();
            g_sense = s;
        } else {
            while (g_sense != s) __nanosleep(32);
        }
        *sense = s;
    }
    __syncthreads();
    __threadfence();
}

// Warp GEMM: one rowtile (16 rows x 32 batch), ksteps [k0,k1).
// B source per kstep: ks<64 -> x0, <128 -> x1, else x2. All B via __ldcg (cross-SM mutable).
__device__ __forceinline__ void warp_gemm(
    const uint32_t* __restrict__ Wt, int nk, int rt, int k0, int k1,
    const uint32_t* __restrict__ x0, const uint32_t* __restrict__ x1,
    const uint32_t* __restrict__ x2, float acc[4][4], int lane)
{
    const uint4* Ap = (const uint4*)(Wt + (((size_t)rt * nk + k0) * 2) * 128) + lane;
    for (int ks = k0; ks < k1; ks++) {
        const uint32_t* xs = (ks < 64) ? x0 : ((ks < 128) ? x1 : x2);
        const uint2* xb = (const uint2*)(xs + (size_t)(ks & 63) * 512);
        uint2 bh[4], bl[4];
        #pragma unroll
        for (int nt = 0; nt < 4; nt++) {
            bh[nt] = __ldcg(&xb[nt * 32 + lane]);
            bl[nt] = __ldcg(&xb[128 + nt * 32 + lane]);
        }
        uint4 ah = __ldg(Ap);
        uint4 al = __ldg(Ap + 32);
        Ap += 64;
        #pragma unroll
        for (int nt = 0; nt < 4; nt++) {
            mma_bf16(acc[nt], (const uint32_t*)&ah, bh[nt].x, bh[nt].y);
            mma_bf16(acc[nt], (const uint32_t*)&ah, bl[nt].x, bl[nt].y);
            mma_bf16(acc[nt], (const uint32_t*)&al, bh[nt].x, bh[nt].y);
        }
    }
}

// Store warp's D fragments into smem tile red[512] = [row16][col32]
__device__ __forceinline__ void acc_to_red(float* red, const float acc[4][4], int lane) {
    int gid = lane >> 2, tig = lane & 3;
    #pragma unroll
    for (int nt = 0; nt < 4; nt++) {
        int c = nt * 8 + tig * 2;
        red[gid * 32 + c]           = acc[nt][0];
        red[gid * 32 + c + 1]       = acc[nt][1];
        red[(gid + 8) * 32 + c]     = acc[nt][2];
        red[(gid + 8) * 32 + c + 1] = acc[nt][3];
    }
}

// LSTM cell tail: block covers hh in [8*bid, 8*bid+8), all 4 gates via permuted rows.
__device__ __forceinline__ void cell_tail(const float (*red)[512],
                                          const float* __restrict__ bih,
                                          const float* __restrict__ bhh,
                                          float* __restrict__ cT, uint32_t* __restrict__ hx,
                                          int bid, int tid)
{
    int hl = tid >> 5, bb = tid & 31;
    float gv[4];
    #pragma unroll
    for (int gt = 0; gt < 4; gt++) {
        int pib = gt * 8 + hl;            // permuted row-in-block
        int par = pib >> 4;               // rowtile parity
        int idx = (pib & 15) * 32 + bb;
        gv[gt] = red[par][idx] + red[par + 2][idx] + red[par + 4][idx] + red[par + 6][idx];
    }
    int hh = bid * 8 + hl;
    float gi = gv[0] + bih[hh]            + bhh[hh];
    float gf = gv[1] + bih[1024 + hh]     + bhh[1024 + hh];
    float gg = gv[2] + bih[2048 + hh]     + bhh[2048 + hh];
    float go = gv[3] + bih[3072 + hh]     + bhh[3072 + hh];
    int e = hh * 32 + bb;
    float cn = sigm(gf) * cT[e] + sigm(gi) * tanhf(gg);
    cT[e] = cn;
    store_x((bf16*)hx, hh, bb, sigm(go) * tanhf(cn));
}

// ---------------- persistent sequence kernel ----------------
__global__ void __launch_bounds__(256, 1)
k_seq(const float* __restrict__ ctx, const int* __restrict__ lens,
      const float* __restrict__ bih0, const float* __restrict__ bhh0,
      const float* __restrict__ bih1, const float* __restrict__ bhh1,
      float* __restrict__ outv, float* __restrict__ attnout)
{
    __shared__ float red[8][512];   // 16KB reduction buffer (reused as qs in attn)
    __shared__ float sc[SS];
    int tid = threadIdx.x, w = tid >> 5, lane = tid & 31;
    int bid = blockIdx.x;
    unsigned sense = 0;

    for (int t = 0; t < TT; t++) {
        int p = t & 1;
        const uint32_t* h0_old = g_h0x[p];
        uint32_t*       h0_new = g_h0x[p ^ 1];
        const uint32_t* h1_old = g_h1x[p];
        uint32_t*       h1_new = g_h1x[p ^ 1];

        // ---- phase 1: gates0 GEMM (K=192) + cell0, in-block ----
        // reads h0_old (ks 128-191), writes h0_new -> no aliasing
        {
            int rt = bid * 2 + (w & 1);
            int kc = w >> 1;                       // 4 k-chunks of 48
            float acc[4][4] = {};
            warp_gemm(g_w0, 192, rt, kc * 48, kc * 48 + 48,
                      g_embx + (size_t)t * 32768, g_feedx, h0_old, acc, lane);
            acc_to_red(red[w], acc, lane);
            __syncthreads();
            cell_tail(red, bih0, bhh0, g_c0T, h0_new, bid, tid);
        }
        gbar(&sense);   // h0_new ready

        // ---- phase 2: gates1 GEMM (K=128) + cell1, in-block ----
        // reads h0_new (ks 0-63) + h1_old (ks 64-127), writes h1_new
        {
            int rt = bid * 2 + (w & 1);
            int kc = w >> 1;                       // 4 k-chunks of 32
            float acc[4][4] = {};
            warp_gemm(g_w1, 128, rt, kc * 32, kc * 32 + 32,
                      h0_new, h1_old, h1_old, acc, lane);
            acc_to_red(red[w], acc, lane);
            __syncthreads();
            cell_tail(red, bih1, bhh1, g_c1T, h1_new, bid, tid);
        }
        gbar(&sense);   // h1_new ready

        // ---- phase 3: q GEMM (blocks 0-63) | out-GEMM h1-half (blocks 64-127) ----
        if (bid < 64) {
            int rt = bid;                          // full K=64, 8-way ksplit in-block
            float acc[4][4] = {};
            warp_gemm(g_wq, 64, rt, w * 8, w * 8 + 8, h1_new, h1_new, h1_new, acc, lane);
            acc_to_red(red[w], acc, lane);
            __syncthreads();
            #pragma unroll
            for (int j = 0; j < 2; j++) {
                int i = tid + j * 256;             // i = r16*32 + bb
                float s = 0.f;
                #pragma unroll
                for (int ww = 0; ww < 8; ww++) s += red[ww][i];
                int row = rt * 16 + (i >> 5), bb = i & 31;
                g_qf[(size_t)bb * HH + row] = s;   // transposed for attn
            }
        } else {
            int rt = bid - 64;
            float acc[4][4] = {};
            warp_gemm(g_wo, 128, rt, 64 + w * 8, 64 + w * 8 + 8,
                      h1_new, h1_new, h1_new, acc, lane);   // ks>=64 -> x1 = h1_new
            acc_to_red(red[w], acc, lane);
            __syncthreads();
            #pragma unroll
            for (int j = 0; j < 2; j++) {
                int i = tid + j * 256;
                float s = 0.f;
                #pragma unroll
                for (int ww = 0; ww < 8; ww++) s += red[ww][i];
                int row = rt * 16 + (i >> 5), bb = i & 31;
                g_po[(size_t)row * 32 + bb] = s;
            }
        }
        gbar(&sense);   // qf, po ready

        // ---- phase 4: attention (blocks 0-31, one batch each) ----
        if (bid < 32) {
            int b = bid;
            float* qs = &red[0][0];                // 1024 floats
            for (int i = tid; i < HH; i += 256)
                qs[i] = __ldcg(&g_qf[(size_t)b * HH + i]);
            __syncthreads();

            #pragma unroll
            for (int si = 0; si < 8; si++) {       // 8 warps x 8 scores
                int s = w * 8 + si;
                const float* cr = ctx + ((size_t)s * BB + b) * HH;
                float sum = 0.f;
                for (int i = lane; i < HH; i += 32) sum = fmaf(qs[i], __ldg(&cr[i]), sum);
                #pragma unroll
                for (int o = 16; o > 0; o >>= 1) sum += __shfl_xor_sync(0xffffffffu, sum, o);
                if (lane == 0) sc[s] = sum;
            }
            __syncthreads();

            if (tid == 0) {
                int len = lens[b];
                len = len < 1 ? 1 : (len > SS ? SS : len);
                float m = sc[0];
                for (int s = 1; s < len; s++) m = fmaxf(m, sc[s]);
                float sum = 0.f;
                for (int s = 0; s < len; s++) { float e = expf(sc[s] - m); sc[s] = e; sum += e; }
                float inv = 1.f / sum;
                for (int s = 0; s < len; s++) sc[s] *= inv;
                for (int s = len; s < SS; s++) sc[s] = 0.f;
            }
            __syncthreads();

            if (tid < SS) attnout[((size_t)t * BB + b) * SS + tid] = sc[tid];

            #pragma unroll
            for (int j = 0; j < 4; j++) {
                int hh = tid + j * 256;
                float a = 0.f;
                for (int s = 0; s < SS; s++)
                    a = fmaf(sc[s], __ldg(&ctx[((size_t)s * BB + b) * HH + hh]), a);
                store_x((bf16*)g_cvx, hh, b, a);
            }
        }
        gbar(&sense);   // cvx ready

        // ---- phase 5: out-GEMM cvec-half + tanh tail (blocks 64-127) ----
        if (bid >= 64) {
            int rt = bid - 64;
            float acc[4][4] = {};
            warp_gemm(g_wo, 128, rt, w * 8, w * 8 + 8, g_cvx, g_cvx, g_cvx, acc, lane);
            acc_to_red(red[w], acc, lane);
            __syncthreads();
            #pragma unroll
            for (int j = 0; j < 2; j++) {
                int i = tid + j * 256;
                float v = 0.f;
                #pragma unroll
                for (int ww = 0; ww < 8; ww++) v += red[ww][i];
                int r16 = i >> 5, bb = i & 31;
                int hh = rt * 16 + r16;
                v += __ldcg(&g_po[(size_t)hh * 32 + bb]);
                v = tanhf(v);
                outv[((size_t)t * BB + bb) * HH + hh] = v;
                store_x((bf16*)g_feedx, hh, bb, v);
            }
        }
        gbar(&sense);   // feedx, outv ready for next step
    }
}

// ---------------- weight conversion: fp32 -> hi/lo A-fragments ----------------
// gatePerm=1: fragment row (rt,i) holds logical gate-row gate*1024 + (rt>>1)*8 + hho
// where pib = (rt&1)*16+i, gate = pib>>3, hho = pib&7  (so each block owns all 4 gates
// of its 8 hh values).
__global__ void k_wconv(const float* __restrict__ W, int ldw,
                        uint32_t* __restrict__ dst, int nkTot, int ksBase, int gatePerm) {
    int rt = blockIdx.x, ks = blockIdx.y;
    int lane = threadIdx.x;
    int gid = lane >> 2, tig = lane & 3;
    uint32_t hi[4], lo[4];
    #pragma unroll
    for (int r = 0; r < 4; r++) {
        int i = gid + (r & 1) * 8;        // row within tile 0..15
        int row;
        if (gatePerm) {
            int pib = (rt & 1) * 16 + i;
            int gate = pib >> 3, hho = pib & 7;
            row = gate * 1024 + (rt >> 1) * 8 + hho;
        } else {
            row = rt * 16 + i;
        }
        int kk = ks * 16 + (r >> 1) * 8 + tig * 2;
        float w0 = __ldg(&W[(size_t)row * ldw + kk]);
        float w1 = __ldg(&W[(size_t)row * ldw + kk + 1]);
        bf16 h0 = __float2bfloat16(w0), h1 = __float2bfloat16(w1);
        bf16 l0 = __float2bfloat16(w0 - __bfloat162float(h0));
        bf16 l1 = __float2bfloat16(w1 - __bfloat162float(h1));
        hi[r] = ((uint32_t)__bfloat16_as_ushort(h1) << 16) | __bfloat16_as_ushort(h0);
        lo[r] = ((uint32_t)__bfloat16_as_ushort(l1) << 16) | __bfloat16_as_ushort(l0);
    }
    size_t bi = (((size_t)rt * nkTot + ksBase + ks) * 2) * 128 + lane * 4;
    #pragma unroll
    for (int r = 0; r < 4; r++) {
        dst[bi + r] = hi[r];
        dst[bi + 128 + r] = lo[r];
    }
}

// ---------------- embedding gather -> B-fragments ----------------
__global__ void k_embx(const int* __restrict__ ids, const float* __restrict__ emb) {
    int t = blockIdx.x;
    int tid = threadIdx.x;
    int b = tid & 31;
    int id = ids[t * BB + b];
    bf16* dstx = (bf16*)(g_embx + (size_t)t * 32768);
    const float* src = emb + (size_t)id * HH;
    for (int hh = tid >> 5; hh < HH; hh += 8)
        store_x(dstx, hh, b, __ldg(&src[hh]));
}

// ---------------- init: states + barrier reset ----------------
__global__ void k_init(const float* __restrict__ h0, const float* __restrict__ c0) {
    int idx = blockIdx.x * 256 + threadIdx.x;
    if (idx == 0) { g_count = 0u; g_sense = 0u; }
    if (idx >= HH * BB) return;
    int hh = idx >> 5, b = idx & 31;
    g_c0T[idx] = c0[(size_t)(0 * BB + b) * HH + hh];
    g_c1T[idx] = c0[(size_t)(1 * BB + b) * HH + hh];
    store_x((bf16*)g_h0x[0], hh, b, h0[(size_t)(0 * BB + b) * HH + hh]);
    store_x((bf16*)g_h1x[0], hh, b, h0[(size_t)(1 * BB + b) * HH + hh]);
    store_x((bf16*)g_feedx, hh, b, 0.f);
}

// ---------------- launcher (graph-capturable: kernel launches only) ----------------
extern "C" void kernel_launch(void* const* d_in, const int* in_sizes, int n_in,
                              void* d_out, int out_size) {
    const int*   ids   = (const int*)  d_in[0];
    const float* ctx   = (const float*)d_in[1];
    const int*   lens  = (const int*)  d_in[2];
    const float* h0    = (const float*)d_in[3];
    const float* c0    = (const float*)d_in[4];
    const float* emb   = (const float*)d_in[5];
    const float* W_ih0 = (const float*)d_in[6];
    const float* W_hh0 = (const float*)d_in[7];
    const float* b_ih0 = (const float*)d_in[8];
    const float* b_hh0 = (const float*)d_in[9];
    const float* W_ih1 = (const float*)d_in[10];
    const float* W_hh1 = (const float*)d_in[11];
    const float* b_ih1 = (const float*)d_in[12];
    const float* b_hh1 = (const float*)d_in[13];
    const float* W_in  = (const float*)d_in[14];
    const float* W_out = (const float*)d_in[15];

    float* outv = (float*)d_out;                      // outputs [T,B,H]
    float* attn = outv + (size_t)TT * BB * HH;        // attns   [T,B,S]

    uint32_t *p_w0, *p_w1, *p_wq, *p_wo;
    cudaGetSymbolAddress((void**)&p_w0, g_w0);
    cudaGetSymbolAddress((void**)&p_w1, g_w1);
    cudaGetSymbolAddress((void**)&p_wq, g_wq);
    cudaGetSymbolAddress((void**)&p_wo, g_wo);

    // One-time conversions (deterministic; rerun every replay)
    k_wconv<<<dim3(256, 128), 32>>>(W_ih0, 2048, p_w0, 192, 0,   1);
    k_wconv<<<dim3(256, 64),  32>>>(W_hh0, 1024, p_w0, 192, 128, 1);
    k_wconv<<<dim3(256, 64),  32>>>(W_ih1, 1024, p_w1, 128, 0,   1);
    k_wconv<<<dim3(256, 64),  32>>>(W_hh1, 1024, p_w1, 128, 64,  1);
    k_wconv<<<dim3(64, 64),   32>>>(W_in,  1024, p_wq, 64,  0,   0);
    k_wconv<<<dim3(64, 128),  32>>>(W_out, 2048, p_wo, 128, 0,   0);
    k_embx<<<TT, 256>>>(ids, emb);
    k_init<<<128, 256>>>(h0, c0);

    // The whole 64-step recurrence: one persistent kernel, 128 co-resident blocks.
    k_seq<<<NBLK, 256>>>(ctx, lens, b_ih0, b_hh0, b_ih1, b_hh1, outv, attn);
}

// round 11
// speedup vs baseline: 5.3563x; 1.1894x over previous
#include <cuda_runtime.h>
#include <cuda_bf16.h>
#include <math.h>
#include <stdint.h>

#define TT 64
#define BB 32
#define SS 64
#define HH 1024
#define NBLK 128

typedef __nv_bfloat16 bf16;

// ---------------- static device scratch (no allocations) ----------------
// Weight fragments (uint32): [rowtile16][kstep][sel hi/lo][lane(32)][reg(4)]
// gates matrices use GATE-PERMUTED row order (see k_wconv).
__device__ uint32_t g_w0[(size_t)256 * 192 * 2 * 128];  // gates0: ks 0-63 W_ih0 emb-half, 64-127 W_ih0 feed-half, 128-191 W_hh0
__device__ uint32_t g_w1[(size_t)256 * 128 * 2 * 128];  // gates1: ks 0-63 W_ih1, 64-127 W_hh1
__device__ uint32_t g_wq[(size_t)64 * 64 * 2 * 128];    // q: W_in
__device__ uint32_t g_wo[(size_t)64 * 128 * 2 * 128];   // out: W_out (ks 0-63 cvec, 64-127 h1)

// Activation B-fragments: per 1024-k vector: [kstep(64)][sel(2)][ntile(4)][lane(32)][reg(2)]
__device__ uint32_t g_embx[(size_t)TT * 32768];
__device__ uint32_t g_h0x[2][32768];   // double-buffered (R9 race fix)
__device__ uint32_t g_h1x[2][32768];
__device__ uint32_t g_feedx[32768];
__device__ uint32_t g_cvx[32768];

__device__ float g_ge[(size_t)TT * 4096 * 32];   // precomputed W_ih0_emb @ emb_t, permuted rows
__device__ float g_c0T[HH * BB];      // [hh][b]
__device__ float g_c1T[HH * BB];
__device__ float g_qf[HH * BB];       // q final, [b][row]
__device__ unsigned g_ctrq[TT];
__device__ unsigned g_ctrcv[TT];
__device__ unsigned g_count;
__device__ volatile unsigned g_sense;

// ---------------- helpers ----------------
__device__ __forceinline__ float sigm(float x) { return 1.f / (1.f + expf(-x)); }

__device__ __forceinline__ void store_x(bf16* base, int hh, int b, float v) {
    int kstep = hh >> 4, kk = hh & 15;
    int ntile = b >> 3, gid = b & 7;
    int reg = kk >> 3, krem = kk & 7, tig = krem >> 1, half = krem & 1;
    int lane = gid * 4 + tig;
    bf16 hi = __float2bfloat16(v);
    bf16 lo = __float2bfloat16(v - __bfloat162float(hi));
    size_t i0 = ((((size_t)kstep * 2 + 0) * 4 + ntile) * 64 + lane * 2 + reg) * 2 + half;
    size_t i1 = ((((size_t)kstep * 2 + 1) * 4 + ntile) * 64 + lane * 2 + reg) * 2 + half;
    base[i0] = hi;
    base[i1] = lo;
}

__device__ __forceinline__ void mma_bf16(float* d, const uint32_t* a, uint32_t b0, uint32_t b1) {
    asm volatile(
        "mma.sync.aligned.m16n8k16.row.col.f32.bf16.bf16.f32 "
        "{%0,%1,%2,%3}, {%4,%5,%6,%7}, {%8,%9}, {%0,%1,%2,%3};"
        : "+f"(d[0]), "+f"(d[1]), "+f"(d[2]), "+f"(d[3])
        : "r"(a[0]), "r"(a[1]), "r"(a[2]), "r"(a[3]), "r"(b0), "r"(b1));
}

// device-wide sense-reversing barrier (all NBLK blocks co-resident)
__device__ __forceinline__ void gbar(unsigned* sense) {
    __syncthreads();
    if (threadIdx.x == 0) {
        unsigned s = *sense ^ 1u;
        __threadfence();
        if (atomicAdd(&g_count, 1u) == (unsigned)(gridDim.x - 1)) {
            g_count = 0u;
            __threadfence();
            g_sense = s;
        } else {
            while (g_sense != s) __nanosleep(32);
        }
        *sense = s;
    }
    __syncthreads();
    __threadfence();
}

__device__ __forceinline__ void arrive_ctr(unsigned* c) {
    __syncthreads();
    if (threadIdx.x == 0) { __threadfence(); atomicAdd(c, 1u); }
}
__device__ __forceinline__ void wait_ctr(unsigned* c, unsigned target) {
    if (threadIdx.x == 0)
        while (*(volatile unsigned*)c < target) __nanosleep(32);
    __syncthreads();
    __threadfence();
}

// 2-rowtile warp GEMM: B loaded once per kstep, used for rt0 and rt0+1 (24 HMMA/kstep).
// routing: ks < split -> xlo else xhi; kstep index = ks & 63.
__device__ __forceinline__ void warp_gemm2(
    const uint32_t* __restrict__ Wt, int nk, int rt0, int k0, int kn, int split,
    const uint32_t* __restrict__ xlo, const uint32_t* __restrict__ xhi,
    float acc[2][4][4], int lane)
{
    const uint4* A0 = (const uint4*)(Wt + (((size_t)rt0 * nk + k0) * 2) * 128) + lane;
    const uint4* A1 = A0 + (size_t)nk * 64;   // rt0+1 (nk*256 uint32 = nk*64 uint4)
    #pragma unroll 4
    for (int s = 0; s < kn; s++) {
        int ks = k0 + s;
        const uint32_t* xs = (ks < split) ? xlo : xhi;
        const uint2* xb = (const uint2*)(xs + (size_t)(ks & 63) * 512);
        uint2 bh[4], bl[4];
        #pragma unroll
        for (int nt = 0; nt < 4; nt++) {
            bh[nt] = __ldcg(&xb[nt * 32 + lane]);
            bl[nt] = __ldcg(&xb[128 + nt * 32 + lane]);
        }
        uint4 ah0 = __ldg(A0), al0 = __ldg(A0 + 32);
        uint4 ah1 = __ldg(A1), al1 = __ldg(A1 + 32);
        A0 += 64; A1 += 64;
        #pragma unroll
        for (int nt = 0; nt < 4; nt++) {
            mma_bf16(acc[0][nt], (const uint32_t*)&ah0, bh[nt].x, bh[nt].y);
            mma_bf16(acc[0][nt], (const uint32_t*)&ah0, bl[nt].x, bl[nt].y);
            mma_bf16(acc[0][nt], (const uint32_t*)&al0, bh[nt].x, bh[nt].y);
            mma_bf16(acc[1][nt], (const uint32_t*)&ah1, bh[nt].x, bh[nt].y);
            mma_bf16(acc[1][nt], (const uint32_t*)&ah1, bl[nt].x, bl[nt].y);
            mma_bf16(acc[1][nt], (const uint32_t*)&al1, bh[nt].x, bh[nt].y);
        }
    }
}

// 1-rowtile warp GEMM (q / out)
__device__ __forceinline__ void warp_gemm1(
    const uint32_t* __restrict__ Wt, int nk, int rt, int k0, int kn,
    const uint32_t* __restrict__ xlo, const uint32_t* __restrict__ xhi,
    float acc[4][4], int lane)
{
    const uint4* Ap = (const uint4*)(Wt + (((size_t)rt * nk + k0) * 2) * 128) + lane;
    #pragma unroll 4
    for (int s = 0; s < kn; s++) {
        int ks = k0 + s;
        const uint32_t* xs = (ks < 64) ? xlo : xhi;
        const uint2* xb = (const uint2*)(xs + (size_t)(ks & 63) * 512);
        uint2 bh[4], bl[4];
        #pragma unroll
        for (int nt = 0; nt < 4; nt++) {
            bh[nt] = __ldcg(&xb[nt * 32 + lane]);
            bl[nt] = __ldcg(&xb[128 + nt * 32 + lane]);
        }
        uint4 ah = __ldg(Ap), al = __ldg(Ap + 32);
        Ap += 64;
        #pragma unroll
        for (int nt = 0; nt < 4; nt++) {
            mma_bf16(acc[nt], (const uint32_t*)&ah, bh[nt].x, bh[nt].y);
            mma_bf16(acc[nt], (const uint32_t*)&ah, bl[nt].x, bl[nt].y);
            mma_bf16(acc[nt], (const uint32_t*)&al, bh[nt].x, bh[nt].y);
        }
    }
}

__device__ __forceinline__ void acc_to_red(float* red, const float acc[4][4], int lane) {
    int gid = lane >> 2, tig = lane & 3;
    #pragma unroll
    for (int nt = 0; nt < 4; nt++) {
        int c = nt * 8 + tig * 2;
        red[gid * 32 + c]           = acc[nt][0];
        red[gid * 32 + c + 1]       = acc[nt][1];
        red[(gid + 8) * 32 + c]     = acc[nt][2];
        red[(gid + 8) * 32 + c + 1] = acc[nt][3];
    }
}

// LSTM cell tail: block covers hh [8*bid, 8*bid+8), all 4 gates via permuted rows.
// red layout: [kc(8)][rtpair(2)][512]; ge != nullptr adds precomputed emb term (P1).
__device__ __forceinline__ void cell_tail(const float (*red)[2][512],
                                          const float* __restrict__ bih,
                                          const float* __restrict__ bhh,
                                          float* __restrict__ cT, uint32_t* __restrict__ hx,
                                          const float* __restrict__ ge,
                                          int bid, int tid)
{
    int hl = tid >> 5, bb = tid & 31;
    float gv[4];
    #pragma unroll
    for (int gt = 0; gt < 4; gt++) {
        int pib = gt * 8 + hl;
        int par = pib >> 4;
        int idx = (pib & 15) * 32 + bb;
        float s = 0.f;
        #pragma unroll
        for (int kc = 0; kc < 8; kc++) s += red[kc][par][idx];
        if (ge) s += __ldg(&ge[(size_t)(bid * 32 + pib) * 32 + bb]);
        gv[gt] = s;
    }
    int hh = bid * 8 + hl;
    float gi = gv[0] + bih[hh]            + bhh[hh];
    float gf = gv[1] + bih[1024 + hh]     + bhh[1024 + hh];
    float gg = gv[2] + bih[2048 + hh]     + bhh[2048 + hh];
    float go = gv[3] + bih[3072 + hh]     + bhh[3072 + hh];
    int e = hh * 32 + bb;
    float cn = sigm(gf) * cT[e] + sigm(gi) * tanhf(gg);
    cT[e] = cn;
    store_x((bf16*)hx, hh, bb, sigm(go) * tanhf(cn));
}

// ---------------- persistent sequence kernel ----------------
__global__ void __launch_bounds__(256, 1)
k_seq(const float* __restrict__ ctx, const int* __restrict__ lens,
      const float* __restrict__ bih0, const float* __restrict__ bhh0,
      const float* __restrict__ bih1, const float* __restrict__ bhh1,
      float* __restrict__ outv, float* __restrict__ attnout)
{
    __shared__ float red[8][2][512];   // 32KB
    __shared__ float sc[SS];
    int tid = threadIdx.x, w = tid >> 5, lane = tid & 31;
    int bid = blockIdx.x;
    unsigned sense = 0;

    for (int t = 0; t < TT; t++) {
        int p = t & 1;
        const uint32_t* h0o = g_h0x[p];
        uint32_t*       h0n = g_h0x[p ^ 1];
        const uint32_t* h1o = g_h1x[p];
        uint32_t*       h1n = g_h1x[p ^ 1];

        // ---- P1: gates0 GEMM (K=128: feed ks64-127, h0 ks128-191) + cell0 ----
        {
            float acc[2][4][4] = {};
            warp_gemm2(g_w0, 192, bid * 2, 64 + w * 16, 16, 128, g_feedx, h0o, acc, lane);
            acc_to_red(red[w][0], acc[0], lane);
            acc_to_red(red[w][1], acc[1], lane);
            __syncthreads();
            cell_tail(red, bih0, bhh0, g_c0T, h0n, g_ge + (size_t)t * 4096 * 32, bid, tid);
        }
        gbar(&sense);   // h0n ready

        // ---- P2: gates1 GEMM (K=128: h0n ks0-63, h1o ks64-127) + cell1 ----
        {
            float acc[2][4][4] = {};
            warp_gemm2(g_w1, 128, bid * 2, w * 16, 16, 64, h0n, h1o, acc, lane);
            acc_to_red(red[w][0], acc[0], lane);
            acc_to_red(red[w][1], acc[1], lane);
            __syncthreads();
            cell_tail(red, bih1, bhh1, g_c1T, h1n, nullptr, bid, tid);
        }
        gbar(&sense);   // h1n ready

        // ---- P3/P4/P5 ----
        if (bid < 64) {
            // q GEMM: M=1024, rt=bid, K=64
            float acc[4][4] = {};
            warp_gemm1(g_wq, 64, bid, w * 8, 8, h1n, h1n, acc, lane);
            acc_to_red(red[w][0], acc, lane);
            __syncthreads();
            #pragma unroll
            for (int j = 0; j < 2; j++) {
                int i = tid + j * 256;
                float s = 0.f;
                #pragma unroll
                for (int ww = 0; ww < 8; ww++) s += red[ww][0][i];
                int row = bid * 16 + (i >> 5), bb = i & 31;
                g_qf[(size_t)bb * HH + row] = s;
            }
            arrive_ctr(&g_ctrq[t]);

            if (bid >= 32) {
                // attention for batch b = bid-32
                wait_ctr(&g_ctrq[t], 64);
                int b = bid - 32;
                float* qs = &red[0][0][0];
                for (int i = tid; i < HH; i += 256)
                    qs[i] = __ldcg(&g_qf[(size_t)b * HH + i]);
                __syncthreads();

                #pragma unroll
                for (int si = 0; si < 8; si++) {
                    int s = w * 8 + si;
                    const float* cr = ctx + ((size_t)s * BB + b) * HH;
                    float sum = 0.f;
                    for (int i = lane; i < HH; i += 32) sum = fmaf(qs[i], __ldg(&cr[i]), sum);
                    #pragma unroll
                    for (int o = 16; o > 0; o >>= 1) sum += __shfl_xor_sync(0xffffffffu, sum, o);
                    if (lane == 0) sc[s] = sum;
                }
                __syncthreads();

                if (tid == 0) {
                    int len = lens[b];
                    len = len < 1 ? 1 : (len > SS ? SS : len);
                    float m = sc[0];
                    for (int s = 1; s < len; s++) m = fmaxf(m, sc[s]);
                    float sum = 0.f;
                    for (int s = 0; s < len; s++) { float e = expf(sc[s] - m); sc[s] = e; sum += e; }
                    float inv = 1.f / sum;
                    for (int s = 0; s < len; s++) sc[s] *= inv;
                    for (int s = len; s < SS; s++) sc[s] = 0.f;
                }
                __syncthreads();

                if (tid < SS) attnout[((size_t)t * BB + b) * SS + tid] = sc[tid];

                #pragma unroll
                for (int j = 0; j < 4; j++) {
                    int hh = tid + j * 256;
                    float a = 0.f;
                    for (int s = 0; s < SS; s++)
                        a = fmaf(sc[s], __ldg(&ctx[((size_t)s * BB + b) * HH + hh]), a);
                    store_x((bf16*)g_cvx, hh, b, a);
                }
                arrive_ctr(&g_ctrcv[t]);
            }
        } else {
            // out GEMM h1-half (no barrier needed before cvx arrives; acc stays in regs)
            int rt = bid - 64;
            float acc[4][4] = {};
            warp_gemm1(g_wo, 128, rt, 64 + w * 8, 8, g_cvx, h1n, acc, lane);
            wait_ctr(&g_ctrcv[t], 32);   // cvx ready
            warp_gemm1(g_wo, 128, rt, w * 8, 8, g_cvx, h1n, acc, lane);
            acc_to_red(red[w][0], acc, lane);
            __syncthreads();
            #pragma unroll
            for (int j = 0; j < 2; j++) {
                int i = tid + j * 256;
                float v = 0.f;
                #pragma unroll
                for (int ww = 0; ww < 8; ww++) v += red[ww][0][i];
                int hh = rt * 16 + (i >> 5), bb = i & 31;
                v = tanhf(v);
                outv[((size_t)t * BB + bb) * HH + hh] = v;
                store_x((bf16*)g_feedx, hh, bb, v);
            }
        }
        gbar(&sense);   // feedx/outv ready for next step
    }
}

// ---------------- prologue: gates0 emb contribution for ALL t (wide-N GEMM) ----------------
// grid (32 Mb, 16 tg), 256 thr. Block: 8 rowtiles (warp each), 4 t, K=64 (emb half of g_w0).
__global__ void __launch_bounds__(256, 1)
k_embgemm() {
    __shared__ uint32_t stage[4][512];   // 8KB: one kstep's B for 4 t
    int tid = threadIdx.x, w = tid >> 5, lane = tid & 31;
    int Mb = blockIdx.x, tg = blockIdx.y;
    int rt = Mb * 8 + w;

    float acc[4][4][4] = {};   // [t][nt][reg]
    const uint4* Ap = (const uint4*)(g_w0 + (((size_t)rt * 192) * 2) * 128) + lane;

    for (int ks = 0; ks < 64; ks++) {
        __syncthreads();
        #pragma unroll
        for (int j = 0; j < 8; j++) {
            int u = tid + j * 256;   // 2048 = 4t x 512
            stage[u >> 9][u & 511] =
                __ldg(&g_embx[(size_t)(tg * 4 + (u >> 9)) * 32768 + (size_t)ks * 512 + (u & 511)]);
        }
        __syncthreads();
        uint4 ah = __ldg(Ap), al = __ldg(Ap + 32);
        Ap += 64;
        #pragma unroll
        for (int tt = 0; tt < 4; tt++) {
            const uint2* xb = (const uint2*)stage[tt];
            #pragma unroll
            for (int nt = 0; nt < 4; nt++) {
                uint2 bh = xb[nt * 32 + lane];
                uint2 bl = xb[128 + nt * 32 + lane];
                mma_bf16(acc[tt][nt], (const uint32_t*)&ah, bh.x, bh.y);
                mma_bf16(acc[tt][nt], (const uint32_t*)&ah, bl.x, bl.y);
                mma_bf16(acc[tt][nt], (const uint32_t*)&al, bh.x, bh.y);
            }
        }
    }

    int gid = lane >> 2, tig = lane & 3;
    #pragma unroll
    for (int tt = 0; tt < 4; tt++) {
        float* gp = g_ge + ((size_t)(tg * 4 + tt) * 4096) * 32;
        #pragma unroll
        for (int nt = 0; nt < 4; nt++) {
            int row0 = rt * 16 + gid, col = nt * 8 + tig * 2;
            *(float2*)&gp[(size_t)row0 * 32 + col] = make_float2(acc[tt][nt][0], acc[tt][nt][1]);
            *(float2*)&gp[(size_t)(row0 + 8) * 32 + col] = make_float2(acc[tt][nt][2], acc[tt][nt][3]);
        }
    }
}

// ---------------- weight conversion: fp32 -> hi/lo A-fragments ----------------
__global__ void k_wconv(const float* __restrict__ W, int ldw,
                        uint32_t* __restrict__ dst, int nkTot, int ksBase, int gatePerm) {
    int rt = blockIdx.x, ks = blockIdx.y;
    int lane = threadIdx.x;
    int gid = lane >> 2, tig = lane & 3;
    uint32_t hi[4], lo[4];
    #pragma unroll
    for (int r = 0; r < 4; r++) {
        int i = gid + (r & 1) * 8;
        int row;
        if (gatePerm) {
            int pib = (rt & 1) * 16 + i;
            int gate = pib >> 3, hho = pib & 7;
            row = gate * 1024 + (rt >> 1) * 8 + hho;
        } else {
            row = rt * 16 + i;
        }
        int kk = ks * 16 + (r >> 1) * 8 + tig * 2;
        float w0 = __ldg(&W[(size_t)row * ldw + kk]);
        float w1 = __ldg(&W[(size_t)row * ldw + kk + 1]);
        bf16 h0 = __float2bfloat16(w0), h1 = __float2bfloat16(w1);
        bf16 l0 = __float2bfloat16(w0 - __bfloat162float(h0));
        bf16 l1 = __float2bfloat16(w1 - __bfloat162float(h1));
        hi[r] = ((uint32_t)__bfloat16_as_ushort(h1) << 16) | __bfloat16_as_ushort(h0);
        lo[r] = ((uint32_t)__bfloat16_as_ushort(l1) << 16) | __bfloat16_as_ushort(l0);
    }
    size_t bi = (((size_t)rt * nkTot + ksBase + ks) * 2) * 128 + lane * 4;
    #pragma unroll
    for (int r = 0; r < 4; r++) {
        dst[bi + r] = hi[r];
        dst[bi + 128 + r] = lo[r];
    }
}

// ---------------- embedding gather -> B-fragments ----------------
__global__ void k_embx(const int* __restrict__ ids, const float* __restrict__ emb) {
    int t = blockIdx.x;
    int tid = threadIdx.x;
    int b = tid & 31;
    int id = ids[t * BB + b];
    bf16* dstx = (bf16*)(g_embx + (size_t)t * 32768);
    const float* src = emb + (size_t)id * HH;
    for (int hh = tid >> 5; hh < HH; hh += 8)
        store_x(dstx, hh, b, __ldg(&src[hh]));
}

// ---------------- init: states + barrier/counter reset ----------------
__global__ void k_init(const float* __restrict__ h0, const float* __restrict__ c0) {
    int idx = blockIdx.x * 256 + threadIdx.x;
    if (idx == 0) { g_count = 0u; g_sense = 0u; }
    if (idx < TT) { g_ctrq[idx] = 0u; g_ctrcv[idx] = 0u; }
    if (idx >= HH * BB) return;
    int hh = idx >> 5, b = idx & 31;
    g_c0T[idx] = c0[(size_t)(0 * BB + b) * HH + hh];
    g_c1T[idx] = c0[(size_t)(1 * BB + b) * HH + hh];
    store_x((bf16*)g_h0x[0], hh, b, h0[(size_t)(0 * BB + b) * HH + hh]);
    store_x((bf16*)g_h1x[0], hh, b, h0[(size_t)(1 * BB + b) * HH + hh]);
    store_x((bf16*)g_feedx, hh, b, 0.f);
}

// ---------------- launcher (graph-capturable: kernel launches only) ----------------
extern "C" void kernel_launch(void* const* d_in, const int* in_sizes, int n_in,
                              void* d_out, int out_size) {
    const int*   ids   = (const int*)  d_in[0];
    const float* ctx   = (const float*)d_in[1];
    const int*   lens  = (const int*)  d_in[2];
    const float* h0    = (const float*)d_in[3];
    const float* c0    = (const float*)d_in[4];
    const float* emb   = (const float*)d_in[5];
    const float* W_ih0 = (const float*)d_in[6];
    const float* W_hh0 = (const float*)d_in[7];
    const float* b_ih0 = (const float*)d_in[8];
    const float* b_hh0 = (const float*)d_in[9];
    const float* W_ih1 = (const float*)d_in[10];
    const float* W_hh1 = (const float*)d_in[11];
    const float* b_ih1 = (const float*)d_in[12];
    const float* b_hh1 = (const float*)d_in[13];
    const float* W_in  = (const float*)d_in[14];
    const float* W_out = (const float*)d_in[15];

    float* outv = (float*)d_out;                      // outputs [T,B,H]
    float* attn = outv + (size_t)TT * BB * HH;        // attns   [T,B,S]

    uint32_t *p_w0, *p_w1, *p_wq, *p_wo;
    cudaGetSymbolAddress((void**)&p_w0, g_w0);
    cudaGetSymbolAddress((void**)&p_w1, g_w1);
    cudaGetSymbolAddress((void**)&p_wq, g_wq);
    cudaGetSymbolAddress((void**)&p_wo, g_wo);

    // One-time conversions (deterministic; rerun every replay)
    k_wconv<<<dim3(256, 128), 32>>>(W_ih0, 2048, p_w0, 192, 0,   1);
    k_wconv<<<dim3(256, 64),  32>>>(W_hh0, 1024, p_w0, 192, 128, 1);
    k_wconv<<<dim3(256, 64),  32>>>(W_ih1, 1024, p_w1, 128, 0,   1);
    k_wconv<<<dim3(256, 64),  32>>>(W_hh1, 1024, p_w1, 128, 64,  1);
    k_wconv<<<dim3(64, 64),   32>>>(W_in,  1024, p_wq, 64,  0,   0);
    k_wconv<<<dim3(64, 128),  32>>>(W_out, 2048, p_wo, 128, 0,   0);
    k_embx<<<TT, 256>>>(ids, emb);
    k_init<<<128, 256>>>(h0, c0);

    // Prologue: gates0 emb contribution for all 64 steps (wide-N GEMM, runs at high eff.)
    k_embgemm<<<dim3(32, 16), 256>>>();

    // The whole 64-step recurrence: one persistent kernel, 128 co-resident blocks.
    k_seq<<<NBLK, 256>>>(ctx, lens, b_ih0, b_hh0, b_ih1, b_hh1, outv, attn);
}